// round 9
// baseline (speedup 1.0000x reference)
#include <cuda_runtime.h>
#include <cuda_fp16.h>
#include <math.h>
#include <stdint.h>

#define D     128
#define D4    32
#define NMAX  50000
#define EMAX  1600000
#define BK    16
#define THREADS 256
#define SB    136   // B smem row stride (floats): proven conflict-free fragment banks
#define SAR   20    // A row-major smem stride: (20g+tig)%32 bijective -> conflict-free

// -------- device scratch (allocation-free rule: __device__ globals) --------
__device__ float  g_x[NMAX * D];      // fp32 x (epilogue math)
__device__ float  g_xtf[NMAX * D];    // tf32-rounded x (GEMM A input)
__device__ __half g_xh[NMAX * D];     // fp16 x (agg gather)
__device__ float  g_xin[NMAX * D];    // tf32-rounded x_in
__device__ float  g_agg[NMAX * D];    // tf32-rounded agg
__device__ float  g_out[NMAX * D];    // tf32-rounded out
__device__ float  g_z[NMAX * D];      // fp32 z
__device__ float  g_wtf[10 * D * D];  // tf32-rounded weights
__device__ int    g_cnt[NMAX];
__device__ int    g_start[NMAX + 1];
__device__ int    g_cur[NMAX];
__device__ int2   g_edges[EMAX];

__device__ __forceinline__ float sigf(float x) { return 1.0f / (1.0f + expf(-x)); }

__device__ __forceinline__ uint32_t f2tf32(float f) {
    uint32_t u;
    asm("cvt.rna.tf32.f32 %0, %1;" : "=r"(u) : "f"(f));
    return u;
}
__device__ __forceinline__ float rtf(float f) { return __uint_as_float(f2tf32(f)); }

__device__ __forceinline__ void mma_tf32(float c[4], const uint32_t a[4],
                                         uint32_t b0, uint32_t b1) {
    asm volatile(
        "mma.sync.aligned.m16n8k8.row.col.f32.tf32.tf32.f32 "
        "{%0,%1,%2,%3}, {%4,%5,%6,%7}, {%8,%9}, {%0,%1,%2,%3};"
        : "+f"(c[0]), "+f"(c[1]), "+f"(c[2]), "+f"(c[3])
        : "r"(a[0]), "r"(a[1]), "r"(a[2]), "r"(a[3]), "r"(b0), "r"(b1));
}

// ---- cp.async helpers ----
__device__ __forceinline__ void cp16(void* dst_smem, const void* src, bool pred) {
    uint32_t dst = (uint32_t)__cvta_generic_to_shared(dst_smem);
    int sz = pred ? 16 : 0;
    asm volatile("cp.async.ca.shared.global [%0], [%1], 16, %2;\n"
                 :: "r"(dst), "l"(src), "r"(sz));
}
__device__ __forceinline__ void cp_commit() {
    asm volatile("cp.async.commit_group;\n");
}
template <int N>
__device__ __forceinline__ void cp_wait() {
    asm volatile("cp.async.wait_group %0;\n" :: "n"(N));
}

// A chunk [row0..+128) x [k0..+16) -> Abuf[row][k] row-major
__device__ __forceinline__ void cpA(const float* __restrict__ A, int row0, int Nrows,
                                    int k0, float* Abuf, int tid) {
#pragma unroll
    for (int q = 0; q < 2; ++q) {
        int idx = tid + q * 256;
        int row = idx >> 2;
        int kq  = (idx & 3) << 2;
        cp16(Abuf + row * SAR + kq,
             A + (size_t)(row0 + row) * D + k0 + kq,
             row0 + row < Nrows);
    }
}

// W chunk [k0..+16) x [0..128) -> Bbuf[k][c]
__device__ __forceinline__ void cpB(const float* __restrict__ W, int k0,
                                    float* Bbuf, int tid) {
#pragma unroll
    for (int q = 0; q < 2; ++q) {
        int idx = tid + q * 256;
        int k  = idx >> 5;
        int c4 = (idx & 31) << 2;
        cp16(Bbuf + k * SB + c4, W + (size_t)(k0 + k) * D + c4, true);
    }
}

// ---- mma over one 16-k chunk; A in row-major smem (stride SAR) ----
__device__ __forceinline__ void mma_chunk_rowA(const float* Ar, const float* Bs,
                                               int m_base, int n_base, int g, int tig,
                                               float acc[2][8][4]) {
#pragma unroll
    for (int ks = 0; ks < 2; ++ks) {
        int k = ks * 8;
        uint32_t afr[2][4];
#pragma unroll
        for (int mt = 0; mt < 2; ++mt) {
            const float* b0p = Ar + (m_base + mt * 16 + g) * SAR + k;
            const float* b1p = b0p + 8 * SAR;
            afr[mt][0] = __float_as_uint(b0p[tig]);
            afr[mt][1] = __float_as_uint(b1p[tig]);
            afr[mt][2] = __float_as_uint(b0p[tig + 4]);
            afr[mt][3] = __float_as_uint(b1p[tig + 4]);
        }
#pragma unroll
        for (int nt = 0; nt < 8; ++nt) {
            int nc = n_base + nt * 8 + g;
            uint32_t b0 = __float_as_uint(Bs[(k + tig) * SB + nc]);
            uint32_t b1 = __float_as_uint(Bs[(k + tig + 4) * SB + nc]);
            mma_tf32(acc[0][nt], afr[0], b0, b1);
            mma_tf32(acc[1][nt], afr[1], b0, b1);
        }
    }
}

// ---- mma over one 16-k chunk; A in [k][row] smem (stride SB) ----
__device__ __forceinline__ void mma_chunk_colA(const float* As, const float* Bs,
                                               int kk_a, int m_base, int n_base,
                                               int g, int tig, float acc[2][8][4]) {
#pragma unroll
    for (int ks = 0; ks < 2; ++ks) {
        int ka = kk_a + ks * 8;
        int kb = ks * 8;
        uint32_t afr[2][4];
#pragma unroll
        for (int mt = 0; mt < 2; ++mt) {
            int mr = m_base + mt * 16 + g;
            afr[mt][0] = __float_as_uint(As[(ka + tig)     * SB + mr]);
            afr[mt][1] = __float_as_uint(As[(ka + tig)     * SB + mr + 8]);
            afr[mt][2] = __float_as_uint(As[(ka + tig + 4) * SB + mr]);
            afr[mt][3] = __float_as_uint(As[(ka + tig + 4) * SB + mr + 8]);
        }
#pragma unroll
        for (int nt = 0; nt < 8; ++nt) {
            int nc = n_base + nt * 8 + g;
            uint32_t b0 = __float_as_uint(Bs[(kb + tig)     * SB + nc]);
            uint32_t b1 = __float_as_uint(Bs[(kb + tig + 4) * SB + nc]);
            mma_tf32(acc[0][nt], afr[0], b0, b1);
            mma_tf32(acc[1][nt], afr[1], b0, b1);
        }
    }
}

#define ABUF_F (128 * SAR)   // 2560 floats per A buffer
#define BBUF_F (BK * SB)     // 2176 floats per B buffer

// Dual-GEMM accumulate, 2-stage cp.async (R7-proven), A/B bufs at smA/smB.
__device__ __forceinline__ void dual_gemm_ca(const float* A1, const float* W1t,
                                             const float* A2, const float* W2t,
                                             float* smA, float* smB,
                                             int row0, int Nrows, int tid,
                                             int m_base, int n_base, int g, int tig,
                                             float acc[2][8][4]) {
    const float* Aarr[2] = {A1, A2};
    const float* Warr[2] = {W1t, W2t};
    float* Ab[2] = {smA, smA + ABUF_F};
    float* Bb[2] = {smB, smB + BBUF_F};

    cpA(Aarr[0], row0, Nrows, 0, Ab[0], tid);
    cpB(Warr[0], 0, Bb[0], tid);
    cp_commit();
#pragma unroll 1
    for (int t = 0; t < 16; ++t) {
        if (t < 15) {
            int tp = t + 1;
            cpA(Aarr[tp >> 3], row0, Nrows, (tp & 7) * BK, Ab[tp & 1], tid);
            cpB(Warr[tp >> 3], (tp & 7) * BK, Bb[tp & 1], tid);
            cp_commit();
            cp_wait<1>();
        } else {
            cp_wait<0>();
        }
        __syncthreads();
        mma_chunk_rowA(Ab[t & 1], Bb[t & 1], m_base, n_base, g, tig, acc);
        __syncthreads();
    }
}

// ===========================================================================
// Fused 2-layer MLP on tensor cores, cp.async 2-stage (R7-proven).
// DUAL: write fp32 to O, tf32 to O2, fp16 to OH.
// ===========================================================================
template <bool DUAL>
__global__ void __launch_bounds__(THREADS, 2)
mlp2_mma_kernel(const float* __restrict__ A,
                const float* __restrict__ W1, const float* __restrict__ b1,
                const float* __restrict__ W2, const float* __restrict__ b2,
                float* __restrict__ O, float* __restrict__ O2,
                __half* __restrict__ OH, int Nrows)
{
    extern __shared__ float sm[];
    float* Ab[2] = {sm, sm + ABUF_F};
    float* Bb[2] = {sm + 2 * ABUF_F, sm + 2 * ABUF_F + BBUF_F};
    float* Hs = sm + 2 * ABUF_F + 2 * BBUF_F;

    int tid  = threadIdx.x;
    int warp = tid >> 5;
    int lane = tid & 31;
    int g    = lane >> 2;
    int tig  = lane & 3;
    int m_base = (warp >> 1) * 32;
    int n_base = (warp & 1) * 64;
    int row0 = blockIdx.x * 128;

    float acc[2][8][4];
#pragma unroll
    for (int mt = 0; mt < 2; ++mt)
#pragma unroll
        for (int nt = 0; nt < 8; ++nt)
#pragma unroll
            for (int i = 0; i < 4; ++i) acc[mt][nt][i] = 0.f;

    cpA(A, row0, Nrows, 0, Ab[0], tid);
    cpB(W1, 0, Bb[0], tid);
    cp_commit();
#pragma unroll 1
    for (int kc = 0; kc < 8; ++kc) {
        if (kc < 7) {
            cpA(A, row0, Nrows, (kc + 1) * BK, Ab[(kc + 1) & 1], tid);
            cpB(W1, (kc + 1) * BK, Bb[(kc + 1) & 1], tid);
            cp_commit();
            cp_wait<1>();
        } else {
            cp_wait<0>();
        }
        __syncthreads();
        mma_chunk_rowA(Ab[kc & 1], Bb[kc & 1], m_base, n_base, g, tig, acc);
        __syncthreads();
    }

    cpB(W2, 0, Bb[0], tid);
    cp_commit();

#pragma unroll
    for (int nt = 0; nt < 8; ++nt) {
        int col = n_base + nt * 8 + 2 * tig;
        float bx = __ldg(&b1[col]);
        float by = __ldg(&b1[col + 1]);
#pragma unroll
        for (int mt = 0; mt < 2; ++mt) {
#pragma unroll
            for (int h = 0; h < 2; ++h) {
                int row = m_base + mt * 16 + g + h * 8;
                Hs[col * SB + row]       = rtf(fmaxf(acc[mt][nt][2 * h]     + bx, 0.f));
                Hs[(col + 1) * SB + row] = rtf(fmaxf(acc[mt][nt][2 * h + 1] + by, 0.f));
                acc[mt][nt][2 * h] = 0.f;
                acc[mt][nt][2 * h + 1] = 0.f;
            }
        }
    }
    __syncthreads();

#pragma unroll 1
    for (int kc = 0; kc < 8; ++kc) {
        if (kc < 7) {
            cpB(W2, (kc + 1) * BK, Bb[(kc + 1) & 1], tid);
            cp_commit();
            cp_wait<1>();
        } else {
            cp_wait<0>();
        }
        __syncthreads();
        mma_chunk_colA(Hs, Bb[kc & 1], kc * BK, m_base, n_base, g, tig, acc);
        __syncthreads();
    }

#pragma unroll
    for (int nt = 0; nt < 8; ++nt) {
        int col = n_base + nt * 8 + 2 * tig;
        float2 bb = make_float2(__ldg(&b2[col]), __ldg(&b2[col + 1]));
#pragma unroll
        for (int mt = 0; mt < 2; ++mt) {
#pragma unroll
            for (int h = 0; h < 2; ++h) {
                int row = row0 + m_base + mt * 16 + g + h * 8;
                if (row >= Nrows) continue;
                float vx = acc[mt][nt][2 * h]     + bb.x;
                float vy = acc[mt][nt][2 * h + 1] + bb.y;
                if (DUAL) {
                    *reinterpret_cast<float2*>(&O[(size_t)row * D + col]) =
                        make_float2(vx, vy);
                    *reinterpret_cast<float2*>(&O2[(size_t)row * D + col]) =
                        make_float2(rtf(vx), rtf(vy));
                    *reinterpret_cast<__half2*>(&OH[(size_t)row * D + col]) =
                        __float22half2_rn(make_float2(vx, vy));
                } else {
                    *reinterpret_cast<float2*>(&O[(size_t)row * D + col]) =
                        make_float2(rtf(vx), rtf(vy));
                }
            }
        }
    }
}

// ===========================================================================
// Merged gate kernel: all three gates in one launch (row-local chain).
//   Phase Z: z = sigmoid(out@Wu1 + x@Wu2 + b) -> g_z
//   Phase R: r = sigmoid(out@Wr1 + x@Wr2 + b); rx = r*x -> SMEM (tf32, colA)
//   Phase O: h = tanh(out@Wo1 + rx@Wo2 + b); final = (1-z)x + z*h -> O
// rx never touches global memory.
// ===========================================================================
__global__ void __launch_bounds__(THREADS, 2)
gate_all_kernel(const float* __restrict__ out_, const float* __restrict__ xtf_,
                const float* __restrict__ wtf,
                const float* __restrict__ bu1, const float* __restrict__ bu2,
                const float* __restrict__ br1, const float* __restrict__ br2,
                const float* __restrict__ bo1, const float* __restrict__ bo2,
                float* __restrict__ O, int Nrows)
{
    extern __shared__ float sm[];
    float* smA = sm;                          // 2 * ABUF_F
    float* smB = sm + 2 * ABUF_F;             // 2 * BBUF_F
    float* Hs  = sm + 2 * ABUF_F + 2 * BBUF_F;  // 128*SB (rx tile)
    float* Ab[2] = {smA, smA + ABUF_F};
    float* Bb[2] = {smB, smB + BBUF_F};

    const float* Wu1 = wtf + (size_t)4 * D * D;
    const float* Wu2 = wtf + (size_t)5 * D * D;
    const float* Wr1 = wtf + (size_t)6 * D * D;
    const float* Wr2 = wtf + (size_t)7 * D * D;
    const float* Wo1 = wtf + (size_t)8 * D * D;
    const float* Wo2 = wtf + (size_t)9 * D * D;

    int tid  = threadIdx.x;
    int warp = tid >> 5;
    int lane = tid & 31;
    int g    = lane >> 2;
    int tig  = lane & 3;
    int m_base = (warp >> 1) * 32;
    int n_base = (warp & 1) * 64;
    int row0 = blockIdx.x * 128;

    const float2* x2 = reinterpret_cast<const float2*>(g_x);

    float acc[2][8][4];
#pragma unroll
    for (int mt = 0; mt < 2; ++mt)
#pragma unroll
        for (int nt = 0; nt < 8; ++nt)
#pragma unroll
            for (int i = 0; i < 4; ++i) acc[mt][nt][i] = 0.f;

    // ---------------- Phase Z ----------------
    dual_gemm_ca(out_, Wu1, xtf_, Wu2, smA, smB, row0, Nrows, tid,
                 m_base, n_base, g, tig, acc);
#pragma unroll
    for (int nt = 0; nt < 8; ++nt) {
        int col = n_base + nt * 8 + 2 * tig;
        float2 bs = make_float2(__ldg(&bu1[col]) + __ldg(&bu2[col]),
                                __ldg(&bu1[col + 1]) + __ldg(&bu2[col + 1]));
#pragma unroll
        for (int mt = 0; mt < 2; ++mt) {
#pragma unroll
            for (int h = 0; h < 2; ++h) {
                int row = row0 + m_base + mt * 16 + g + h * 8;
                if (row < Nrows) {
                    size_t p = (size_t)row * 64 + (col >> 1);
                    reinterpret_cast<float2*>(g_z)[p] =
                        make_float2(sigf(acc[mt][nt][2 * h] + bs.x),
                                    sigf(acc[mt][nt][2 * h + 1] + bs.y));
                }
                acc[mt][nt][2 * h] = 0.f;
                acc[mt][nt][2 * h + 1] = 0.f;
            }
        }
    }

    // ---------------- Phase R ----------------
    dual_gemm_ca(out_, Wr1, xtf_, Wr2, smA, smB, row0, Nrows, tid,
                 m_base, n_base, g, tig, acc);
#pragma unroll
    for (int nt = 0; nt < 8; ++nt) {
        int col = n_base + nt * 8 + 2 * tig;
        float2 bs = make_float2(__ldg(&br1[col]) + __ldg(&br2[col]),
                                __ldg(&br1[col + 1]) + __ldg(&br2[col + 1]));
#pragma unroll
        for (int mt = 0; mt < 2; ++mt) {
#pragma unroll
            for (int h = 0; h < 2; ++h) {
                int rloc = m_base + mt * 16 + g + h * 8;
                int row = row0 + rloc;
                float2 xv = make_float2(0.f, 0.f);
                if (row < Nrows) xv = x2[(size_t)row * 64 + (col >> 1)];
                float rx0 = sigf(acc[mt][nt][2 * h]     + bs.x) * xv.x;
                float rx1 = sigf(acc[mt][nt][2 * h + 1] + bs.y) * xv.y;
                Hs[col * SB + rloc]       = rtf(rx0);
                Hs[(col + 1) * SB + rloc] = rtf(rx1);
                acc[mt][nt][2 * h] = 0.f;
                acc[mt][nt][2 * h + 1] = 0.f;
            }
        }
    }
    __syncthreads();   // publish Hs(rx) before Phase O pass 2 reads it

    // ---------------- Phase O ----------------
    // pass 1: out @ Wo1 (rowA, A+B 2-stage)
    cpA(out_, row0, Nrows, 0, Ab[0], tid);
    cpB(Wo1, 0, Bb[0], tid);
    cp_commit();
#pragma unroll 1
    for (int kc = 0; kc < 8; ++kc) {
        if (kc < 7) {
            cpA(out_, row0, Nrows, (kc + 1) * BK, Ab[(kc + 1) & 1], tid);
            cpB(Wo1, (kc + 1) * BK, Bb[(kc + 1) & 1], tid);
            cp_commit();
            cp_wait<1>();
        } else {
            cp_wait<0>();
        }
        __syncthreads();
        mma_chunk_rowA(Ab[kc & 1], Bb[kc & 1], m_base, n_base, g, tig, acc);
        __syncthreads();
    }
    // pass 2: rx(Hs) @ Wo2 (colA, B-only 2-stage)
    cpB(Wo2, 0, Bb[0], tid);
    cp_commit();
#pragma unroll 1
    for (int kc = 0; kc < 8; ++kc) {
        if (kc < 7) {
            cpB(Wo2, (kc + 1) * BK, Bb[(kc + 1) & 1], tid);
            cp_commit();
            cp_wait<1>();
        } else {
            cp_wait<0>();
        }
        __syncthreads();
        mma_chunk_colA(Hs, Bb[kc & 1], kc * BK, m_base, n_base, g, tig, acc);
        __syncthreads();
    }

    const float2* z2 = reinterpret_cast<const float2*>(g_z);
#pragma unroll
    for (int nt = 0; nt < 8; ++nt) {
        int col = n_base + nt * 8 + 2 * tig;
        float2 bs = make_float2(__ldg(&bo1[col]) + __ldg(&bo2[col]),
                                __ldg(&bo1[col + 1]) + __ldg(&bo2[col + 1]));
#pragma unroll
        for (int mt = 0; mt < 2; ++mt) {
#pragma unroll
            for (int h = 0; h < 2; ++h) {
                int row = row0 + m_base + mt * 16 + g + h * 8;
                if (row >= Nrows) continue;
                float tx = acc[mt][nt][2 * h]     + bs.x;
                float ty = acc[mt][nt][2 * h + 1] + bs.y;
                size_t p = (size_t)row * 64 + (col >> 1);
                float2 xv = x2[p];
                float2 zv = z2[p];
                float2 o;
                o.x = (1.f - zv.x) * xv.x + zv.x * tanhf(tx);
                o.y = (1.f - zv.y) * xv.y + zv.y * tanhf(ty);
                reinterpret_cast<float2*>(O)[p] = o;
            }
        }
    }
}

// ===========================================================================
// Conversions
// ===========================================================================
__global__ void cvtw_kernel(const float* w0, const float* w1, const float* w2,
                            const float* w3, const float* w4, const float* w5,
                            const float* w6, const float* w7, const float* w8,
                            const float* w9, float* dst)
{
    const float* ws[10] = {w0, w1, w2, w3, w4, w5, w6, w7, w8, w9};
    const float* w = ws[blockIdx.y];
    int i = blockIdx.x * 256 + threadIdx.x;
    dst[(size_t)blockIdx.y * D * D + i] = rtf(w[i]);
}

__global__ void cvtx_kernel(const float* __restrict__ src, float* __restrict__ dst, int n4)
{
    int i = blockIdx.x * blockDim.x + threadIdx.x;
    if (i < n4) {
        float4 v = reinterpret_cast<const float4*>(src)[i];
        reinterpret_cast<float4*>(dst)[i] =
            make_float4(rtf(v.x), rtf(v.y), rtf(v.z), rtf(v.w));
    }
}

// ===========================================================================
// CSR build + atomic-free aggregation
// ===========================================================================
__global__ void zero_cnt_kernel(int Nn)
{
    int i = blockIdx.x * blockDim.x + threadIdx.x;
    if (i < Nn) g_cnt[i] = 0;
}

__global__ void count_kernel(const int* __restrict__ rows, int E)
{
    int e = blockIdx.x * blockDim.x + threadIdx.x;
    if (e < E) atomicAdd(&g_cnt[rows[e]], 1);
}

__global__ void scan_kernel(int Nn)
{
    __shared__ int warp_tot[32];
    int t = threadIdx.x;
    int lane = t & 31, w = t >> 5;
    int C = (Nn + 1023) / 1024;
    int lo = t * C;
    int hi = min(lo + C, Nn);

    int sum = 0;
    for (int i = lo; i < hi; ++i) sum += g_cnt[i];

    int v = sum;
#pragma unroll
    for (int o = 1; o < 32; o <<= 1) {
        int u = __shfl_up_sync(0xffffffffu, v, o);
        if (lane >= o) v += u;
    }
    if (lane == 31) warp_tot[w] = v;
    __syncthreads();
    if (w == 0) {
        int tv = warp_tot[lane];
#pragma unroll
        for (int o = 1; o < 32; o <<= 1) {
            int u = __shfl_up_sync(0xffffffffu, tv, o);
            if (lane >= o) tv += u;
        }
        warp_tot[lane] = tv;
    }
    __syncthreads();
    int incl = v + (w > 0 ? warp_tot[w - 1] : 0);
    int run = incl - sum;

    for (int i = lo; i < hi; ++i) {
        int c = g_cnt[i];
        g_start[i] = run;
        g_cur[i] = run;
        run += c;
    }
    if (t == 1023) g_start[Nn] = run;
}

__global__ void fill_kernel(const int* __restrict__ rows, const int* __restrict__ cols,
                            const float* __restrict__ vals, int E)
{
    int e = blockIdx.x * blockDim.x + threadIdx.x;
    if (e < E) {
        int r = rows[e];
        int pos = atomicAdd(&g_cur[r], 1);
        g_edges[pos] = make_int2(cols[e], __float_as_int(vals[e]));
    }
}

// Warp per node; fp16 gather; 4 edges in flight (MLP=4).
__global__ void agg_kernel(const __half* __restrict__ xh, float* __restrict__ agg, int Nn)
{
    int gw = (blockIdx.x * blockDim.x + threadIdx.x) >> 5;
    int lane = threadIdx.x & 31;
    if (gw >= Nn) return;

    int s = __ldg(&g_start[gw]);
    int t = __ldg(&g_start[gw + 1]);
    const uint2* x2 = reinterpret_cast<const uint2*>(xh);

    float4 acc = make_float4(0.f, 0.f, 0.f, 0.f);
    int j = s;
    for (; j + 4 <= t; j += 4) {
        int2 e0 = __ldg(&g_edges[j]);
        int2 e1 = __ldg(&g_edges[j + 1]);
        int2 e2 = __ldg(&g_edges[j + 2]);
        int2 e3 = __ldg(&g_edges[j + 3]);
        uint2 u0 = x2[(size_t)e0.x * 32 + lane];
        uint2 u1 = x2[(size_t)e1.x * 32 + lane];
        uint2 u2 = x2[(size_t)e2.x * 32 + lane];
        uint2 u3 = x2[(size_t)e3.x * 32 + lane];
        float v0 = __int_as_float(e0.y);
        float v1 = __int_as_float(e1.y);
        float v2 = __int_as_float(e2.y);
        float v3 = __int_as_float(e3.y);
        {
            float2 a = __half22float2(*reinterpret_cast<__half2*>(&u0.x));
            float2 b = __half22float2(*reinterpret_cast<__half2*>(&u0.y));
            acc.x += v0 * a.x; acc.y += v0 * a.y; acc.z += v0 * b.x; acc.w += v0 * b.y;
        }
        {
            float2 a = __half22float2(*reinterpret_cast<__half2*>(&u1.x));
            float2 b = __half22float2(*reinterpret_cast<__half2*>(&u1.y));
            acc.x += v1 * a.x; acc.y += v1 * a.y; acc.z += v1 * b.x; acc.w += v1 * b.y;
        }
        {
            float2 a = __half22float2(*reinterpret_cast<__half2*>(&u2.x));
            float2 b = __half22float2(*reinterpret_cast<__half2*>(&u2.y));
            acc.x += v2 * a.x; acc.y += v2 * a.y; acc.z += v2 * b.x; acc.w += v2 * b.y;
        }
        {
            float2 a = __half22float2(*reinterpret_cast<__half2*>(&u3.x));
            float2 b = __half22float2(*reinterpret_cast<__half2*>(&u3.y));
            acc.x += v3 * a.x; acc.y += v3 * a.y; acc.z += v3 * b.x; acc.w += v3 * b.y;
        }
    }
    for (; j < t; ++j) {
        int2 ea = __ldg(&g_edges[j]);
        uint2 ua = x2[(size_t)ea.x * 32 + lane];
        float va = __int_as_float(ea.y);
        float2 a = __half22float2(*reinterpret_cast<__half2*>(&ua.x));
        float2 b = __half22float2(*reinterpret_cast<__half2*>(&ua.y));
        acc.x += va * a.x; acc.y += va * a.y; acc.z += va * b.x; acc.w += va * b.y;
    }
    reinterpret_cast<float4*>(agg)[(size_t)gw * D4 + lane] =
        make_float4(rtf(acc.x), rtf(acc.y), rtf(acc.z), rtf(acc.w));
}

// ---------------------------------------------------------------------------
extern "C" void kernel_launch(void* const* d_in, const int* in_sizes, int n_in,
                              void* d_out, int out_size)
{
    const float* x_in  = (const float*)d_in[0];
    const int*   rows  = (const int*)  d_in[1];
    const int*   cols  = (const int*)  d_in[2];
    const float* vals  = (const float*)d_in[3];
    const float* m1_W1 = (const float*)d_in[4];
    const float* m1_b1 = (const float*)d_in[5];
    const float* m1_W2 = (const float*)d_in[6];
    const float* m1_b2 = (const float*)d_in[7];
    const float* m2_W1 = (const float*)d_in[8];
    const float* m2_b1 = (const float*)d_in[9];
    const float* m2_W2 = (const float*)d_in[10];
    const float* m2_b2 = (const float*)d_in[11];
    const float* Wu1   = (const float*)d_in[12];
    const float* bu1   = (const float*)d_in[13];
    const float* Wu2   = (const float*)d_in[14];
    const float* bu2   = (const float*)d_in[15];
    const float* Wr1   = (const float*)d_in[16];
    const float* br1   = (const float*)d_in[17];
    const float* Wr2   = (const float*)d_in[18];
    const float* br2   = (const float*)d_in[19];
    const float* Wo1   = (const float*)d_in[20];
    const float* bo1   = (const float*)d_in[21];
    const float* Wo2   = (const float*)d_in[22];
    const float* bo2   = (const float*)d_in[23];

    int N = in_sizes[0] / D;
    int E = in_sizes[1];

    float *px, *pxtf, *pxin, *pagg, *pout, *pwtf;
    __half* pxh;
    cudaGetSymbolAddress((void**)&px,   g_x);
    cudaGetSymbolAddress((void**)&pxtf, g_xtf);
    cudaGetSymbolAddress((void**)&pxh,  g_xh);
    cudaGetSymbolAddress((void**)&pxin, g_xin);
    cudaGetSymbolAddress((void**)&pagg, g_agg);
    cudaGetSymbolAddress((void**)&pout, g_out);
    cudaGetSymbolAddress((void**)&pwtf, g_wtf);

    static cudaStream_t s_side = nullptr;
    static cudaEvent_t ev_fork = nullptr, ev_join = nullptr;
    if (!s_side) {
        cudaStreamCreateWithFlags(&s_side, cudaStreamNonBlocking);
        cudaEventCreateWithFlags(&ev_fork, cudaEventDisableTiming);
        cudaEventCreateWithFlags(&ev_join, cudaEventDisableTiming);
    }

    int smem_big = (2 * ABUF_F + 2 * BBUF_F + 128 * SB) * (int)sizeof(float);  // 107520 B
    cudaFuncSetAttribute(mlp2_mma_kernel<true>,  cudaFuncAttributeMaxDynamicSharedMemorySize, smem_big);
    cudaFuncSetAttribute(mlp2_mma_kernel<false>, cudaFuncAttributeMaxDynamicSharedMemorySize, smem_big);
    cudaFuncSetAttribute(gate_all_kernel,        cudaFuncAttributeMaxDynamicSharedMemorySize, smem_big);

    int nblk = (N + 127) / 128;
    int eblk = (E + 255) / 256;
    int n4 = N * D / 4;

    // ---- fork: CSR build on side stream ----
    cudaEventRecord(ev_fork, 0);
    cudaStreamWaitEvent(s_side, ev_fork, 0);
    zero_cnt_kernel<<<(N + 255) / 256, 256, 0, s_side>>>(N);
    count_kernel<<<eblk, 256, 0, s_side>>>(rows, E);
    scan_kernel<<<1, 1024, 0, s_side>>>(N);
    fill_kernel<<<eblk, 256, 0, s_side>>>(rows, cols, vals, E);
    cudaEventRecord(ev_join, s_side);

    // ---- main: conversions, then pipeline ----
    dim3 wgrid(64, 10);
    cvtw_kernel<<<wgrid, 256>>>(m1_W1, m1_W2, m2_W1, m2_W2, Wu1, Wu2, Wr1, Wr2, Wo1, Wo2, pwtf);
    cvtx_kernel<<<(n4 + 255) / 256, 256>>>(x_in, pxin, n4);

    mlp2_mma_kernel<true><<<nblk, THREADS, smem_big>>>(
        pxin, pwtf + 0 * D * D, m1_b1, pwtf + 1 * D * D, m1_b2, px, pxtf, pxh, N);

    cudaStreamWaitEvent(0, ev_join, 0);
    agg_kernel<<<(N * 32 + 255) / 256, 256>>>(pxh, pagg, N);

    mlp2_mma_kernel<false><<<nblk, THREADS, smem_big>>>(
        pagg, pwtf + 2 * D * D, m2_b1, pwtf + 3 * D * D, m2_b2, pout, nullptr, nullptr, N);

    gate_all_kernel<<<nblk, THREADS, smem_big>>>(
        pout, pxtf, pwtf, bu1, bu2, br1, br2, bo1, bo2, (float*)d_out, N);
}

// round 10
// speedup vs baseline: 1.0811x; 1.0811x over previous
#include <cuda_runtime.h>
#include <cuda_fp16.h>
#include <math.h>
#include <stdint.h>

#define D     128
#define D4    32
#define NMAX  50000
#define EMAX  1600000
#define BK    16
#define THREADS 256
#define SB    136   // B smem row stride (floats): proven conflict-free fragment banks
#define SAR   20    // A row-major smem stride: (20g+tig)%32 bijective -> conflict-free

// -------- device scratch (allocation-free rule: __device__ globals) --------
__device__ float  g_x[NMAX * D];      // fp32 x (epilogue math)
__device__ float  g_xtf[NMAX * D];    // tf32-rounded x (GEMM A input)
__device__ __half g_xh[NMAX * D];     // fp16 x (agg gather)
__device__ float  g_xin[NMAX * D];    // tf32-rounded x_in
__device__ float  g_agg[NMAX * D];    // tf32-rounded agg
__device__ float  g_out[NMAX * D];    // tf32-rounded out
__device__ float  g_z[NMAX * D];      // fp32 z
__device__ float  g_rx[NMAX * D];     // tf32-rounded r*x
__device__ float  g_wtf[10 * D * D];  // tf32-rounded weights
__device__ int    g_cnt[NMAX];
__device__ int    g_start[NMAX + 1];
__device__ int    g_cur[NMAX];
__device__ int2   g_edges[EMAX];

__device__ __forceinline__ float sigf(float x) { return 1.0f / (1.0f + expf(-x)); }

__device__ __forceinline__ uint32_t f2tf32(float f) {
    uint32_t u;
    asm("cvt.rna.tf32.f32 %0, %1;" : "=r"(u) : "f"(f));
    return u;
}
__device__ __forceinline__ float rtf(float f) { return __uint_as_float(f2tf32(f)); }

__device__ __forceinline__ void mma_tf32(float c[4], const uint32_t a[4],
                                         uint32_t b0, uint32_t b1) {
    asm volatile(
        "mma.sync.aligned.m16n8k8.row.col.f32.tf32.tf32.f32 "
        "{%0,%1,%2,%3}, {%4,%5,%6,%7}, {%8,%9}, {%0,%1,%2,%3};"
        : "+f"(c[0]), "+f"(c[1]), "+f"(c[2]), "+f"(c[3])
        : "r"(a[0]), "r"(a[1]), "r"(a[2]), "r"(a[3]), "r"(b0), "r"(b1));
}

// ---- cp.async helpers ----
__device__ __forceinline__ void cp16(void* dst_smem, const void* src, bool pred) {
    uint32_t dst = (uint32_t)__cvta_generic_to_shared(dst_smem);
    int sz = pred ? 16 : 0;
    asm volatile("cp.async.ca.shared.global [%0], [%1], 16, %2;\n"
                 :: "r"(dst), "l"(src), "r"(sz));
}
__device__ __forceinline__ void cp_commit() {
    asm volatile("cp.async.commit_group;\n");
}
template <int N>
__device__ __forceinline__ void cp_wait() {
    asm volatile("cp.async.wait_group %0;\n" :: "n"(N));
}

// A chunk [row0..+128) x [k0..+16) -> Abuf[row][k] row-major
__device__ __forceinline__ void cpA(const float* __restrict__ A, int row0, int Nrows,
                                    int k0, float* Abuf, int tid) {
#pragma unroll
    for (int q = 0; q < 2; ++q) {
        int idx = tid + q * 256;
        int row = idx >> 2;
        int kq  = (idx & 3) << 2;
        cp16(Abuf + row * SAR + kq,
             A + (size_t)(row0 + row) * D + k0 + kq,
             row0 + row < Nrows);
    }
}

// W chunk [k0..+16) x [0..128) -> Bbuf[k][c]
__device__ __forceinline__ void cpB(const float* __restrict__ W, int k0,
                                    float* Bbuf, int tid) {
#pragma unroll
    for (int q = 0; q < 2; ++q) {
        int idx = tid + q * 256;
        int k  = idx >> 5;
        int c4 = (idx & 31) << 2;
        cp16(Bbuf + k * SB + c4, W + (size_t)(k0 + k) * D + c4, true);
    }
}

// ---- mma over one 16-k chunk; A in row-major smem (stride SAR) ----
__device__ __forceinline__ void mma_chunk_rowA(const float* Ar, const float* Bs,
                                               int m_base, int n_base, int g, int tig,
                                               float acc[2][8][4]) {
#pragma unroll
    for (int ks = 0; ks < 2; ++ks) {
        int k = ks * 8;
        uint32_t afr[2][4];
#pragma unroll
        for (int mt = 0; mt < 2; ++mt) {
            const float* b0p = Ar + (m_base + mt * 16 + g) * SAR + k;
            const float* b1p = b0p + 8 * SAR;
            afr[mt][0] = __float_as_uint(b0p[tig]);
            afr[mt][1] = __float_as_uint(b1p[tig]);
            afr[mt][2] = __float_as_uint(b0p[tig + 4]);
            afr[mt][3] = __float_as_uint(b1p[tig + 4]);
        }
#pragma unroll
        for (int nt = 0; nt < 8; ++nt) {
            int nc = n_base + nt * 8 + g;
            uint32_t b0 = __float_as_uint(Bs[(k + tig) * SB + nc]);
            uint32_t b1 = __float_as_uint(Bs[(k + tig + 4) * SB + nc]);
            mma_tf32(acc[0][nt], afr[0], b0, b1);
            mma_tf32(acc[1][nt], afr[1], b0, b1);
        }
    }
}

// ---- mma over one 16-k chunk; A in [k][row] smem (stride SB) ----
__device__ __forceinline__ void mma_chunk_colA(const float* As, const float* Bs,
                                               int kk_a, int m_base, int n_base,
                                               int g, int tig, float acc[2][8][4]) {
#pragma unroll
    for (int ks = 0; ks < 2; ++ks) {
        int ka = kk_a + ks * 8;
        int kb = ks * 8;
        uint32_t afr[2][4];
#pragma unroll
        for (int mt = 0; mt < 2; ++mt) {
            int mr = m_base + mt * 16 + g;
            afr[mt][0] = __float_as_uint(As[(ka + tig)     * SB + mr]);
            afr[mt][1] = __float_as_uint(As[(ka + tig)     * SB + mr + 8]);
            afr[mt][2] = __float_as_uint(As[(ka + tig + 4) * SB + mr]);
            afr[mt][3] = __float_as_uint(As[(ka + tig + 4) * SB + mr + 8]);
        }
#pragma unroll
        for (int nt = 0; nt < 8; ++nt) {
            int nc = n_base + nt * 8 + g;
            uint32_t b0 = __float_as_uint(Bs[(kb + tig)     * SB + nc]);
            uint32_t b1 = __float_as_uint(Bs[(kb + tig + 4) * SB + nc]);
            mma_tf32(acc[0][nt], afr[0], b0, b1);
            mma_tf32(acc[1][nt], afr[1], b0, b1);
        }
    }
}

#define ABUF_F (128 * SAR)   // 2560 floats per A buffer
#define BBUF_F (BK * SB)     // 2176 floats per B buffer

// Dual-GEMM accumulate, 2-stage cp.async (R7-PROVEN shape).
__device__ __forceinline__ void dual_gemm_ca(const float* A1, const float* W1t,
                                             const float* A2, const float* W2t,
                                             float* smA, float* smB,
                                             int row0, int Nrows, int tid,
                                             int m_base, int n_base, int g, int tig,
                                             float acc[2][8][4]) {
    const float* Aarr[2] = {A1, A2};
    const float* Warr[2] = {W1t, W2t};
    float* Ab[2] = {smA, smA + ABUF_F};
    float* Bb[2] = {smB, smB + BBUF_F};

    cpA(Aarr[0], row0, Nrows, 0, Ab[0], tid);
    cpB(Warr[0], 0, Bb[0], tid);
    cp_commit();
#pragma unroll 1
    for (int t = 0; t < 16; ++t) {
        if (t < 15) {
            int tp = t + 1;
            cpA(Aarr[tp >> 3], row0, Nrows, (tp & 7) * BK, Ab[tp & 1], tid);
            cpB(Warr[tp >> 3], (tp & 7) * BK, Bb[tp & 1], tid);
            cp_commit();
            cp_wait<1>();
        } else {
            cp_wait<0>();
        }
        __syncthreads();
        mma_chunk_rowA(Ab[t & 1], Bb[t & 1], m_base, n_base, g, tig, acc);
        __syncthreads();
    }
}

// ===========================================================================
// Fused 2-layer MLP on tensor cores, cp.async 2-stage (R7-proven).
// DUAL: write fp32 to O, tf32 to O2, fp16 to OH.
// ===========================================================================
template <bool DUAL>
__global__ void __launch_bounds__(THREADS, 2)
mlp2_mma_kernel(const float* __restrict__ A,
                const float* __restrict__ W1, const float* __restrict__ b1,
                const float* __restrict__ W2, const float* __restrict__ b2,
                float* __restrict__ O, float* __restrict__ O2,
                __half* __restrict__ OH, int Nrows)
{
    extern __shared__ float sm[];
    float* Ab[2] = {sm, sm + ABUF_F};
    float* Bb[2] = {sm + 2 * ABUF_F, sm + 2 * ABUF_F + BBUF_F};
    float* Hs = sm + 2 * ABUF_F + 2 * BBUF_F;

    int tid  = threadIdx.x;
    int warp = tid >> 5;
    int lane = tid & 31;
    int g    = lane >> 2;
    int tig  = lane & 3;
    int m_base = (warp >> 1) * 32;
    int n_base = (warp & 1) * 64;
    int row0 = blockIdx.x * 128;

    float acc[2][8][4];
#pragma unroll
    for (int mt = 0; mt < 2; ++mt)
#pragma unroll
        for (int nt = 0; nt < 8; ++nt)
#pragma unroll
            for (int i = 0; i < 4; ++i) acc[mt][nt][i] = 0.f;

    cpA(A, row0, Nrows, 0, Ab[0], tid);
    cpB(W1, 0, Bb[0], tid);
    cp_commit();
#pragma unroll 1
    for (int kc = 0; kc < 8; ++kc) {
        if (kc < 7) {
            cpA(A, row0, Nrows, (kc + 1) * BK, Ab[(kc + 1) & 1], tid);
            cpB(W1, (kc + 1) * BK, Bb[(kc + 1) & 1], tid);
            cp_commit();
            cp_wait<1>();
        } else {
            cp_wait<0>();
        }
        __syncthreads();
        mma_chunk_rowA(Ab[kc & 1], Bb[kc & 1], m_base, n_base, g, tig, acc);
        __syncthreads();
    }

    cpB(W2, 0, Bb[0], tid);
    cp_commit();

#pragma unroll
    for (int nt = 0; nt < 8; ++nt) {
        int col = n_base + nt * 8 + 2 * tig;
        float bx = __ldg(&b1[col]);
        float by = __ldg(&b1[col + 1]);
#pragma unroll
        for (int mt = 0; mt < 2; ++mt) {
#pragma unroll
            for (int h = 0; h < 2; ++h) {
                int row = m_base + mt * 16 + g + h * 8;
                Hs[col * SB + row]       = rtf(fmaxf(acc[mt][nt][2 * h]     + bx, 0.f));
                Hs[(col + 1) * SB + row] = rtf(fmaxf(acc[mt][nt][2 * h + 1] + by, 0.f));
                acc[mt][nt][2 * h] = 0.f;
                acc[mt][nt][2 * h + 1] = 0.f;
            }
        }
    }
    __syncthreads();

#pragma unroll 1
    for (int kc = 0; kc < 8; ++kc) {
        if (kc < 7) {
            cpB(W2, (kc + 1) * BK, Bb[(kc + 1) & 1], tid);
            cp_commit();
            cp_wait<1>();
        } else {
            cp_wait<0>();
        }
        __syncthreads();
        mma_chunk_colA(Hs, Bb[kc & 1], kc * BK, m_base, n_base, g, tig, acc);
        __syncthreads();
    }

#pragma unroll
    for (int nt = 0; nt < 8; ++nt) {
        int col = n_base + nt * 8 + 2 * tig;
        float2 bb = make_float2(__ldg(&b2[col]), __ldg(&b2[col + 1]));
#pragma unroll
        for (int mt = 0; mt < 2; ++mt) {
#pragma unroll
            for (int h = 0; h < 2; ++h) {
                int row = row0 + m_base + mt * 16 + g + h * 8;
                if (row >= Nrows) continue;
                float vx = acc[mt][nt][2 * h]     + bb.x;
                float vy = acc[mt][nt][2 * h + 1] + bb.y;
                if (DUAL) {
                    *reinterpret_cast<float2*>(&O[(size_t)row * D + col]) =
                        make_float2(vx, vy);
                    *reinterpret_cast<float2*>(&O2[(size_t)row * D + col]) =
                        make_float2(rtf(vx), rtf(vy));
                    *reinterpret_cast<__half2*>(&OH[(size_t)row * D + col]) =
                        __float22half2_rn(make_float2(vx, vy));
                } else {
                    *reinterpret_cast<float2*>(&O[(size_t)row * D + col]) =
                        make_float2(rtf(vx), rtf(vy));
                }
            }
        }
    }
}

// ===========================================================================
// Merged z/r gate kernel (gridDim.y = 2), R7-proven structure.
// ===========================================================================
__global__ void __launch_bounds__(THREADS, 2)
gate01_mma_kernel(const float* __restrict__ out_, const float* __restrict__ xtf_,
                  const float* __restrict__ wtf,
                  const float* __restrict__ bu1, const float* __restrict__ bu2,
                  const float* __restrict__ br1, const float* __restrict__ br2,
                  int Nrows)
{
    __shared__ float smA[2 * ABUF_F];
    __shared__ float smB[2 * BBUF_F];

    int mode = blockIdx.y;
    const float* Wa = wtf + (size_t)(4 + 2 * mode) * D * D;
    const float* Wb = wtf + (size_t)(5 + 2 * mode) * D * D;
    const float* ba = mode ? br1 : bu1;
    const float* bb_ = mode ? br2 : bu2;

    int tid  = threadIdx.x;
    int warp = tid >> 5;
    int lane = tid & 31;
    int g    = lane >> 2;
    int tig  = lane & 3;
    int m_base = (warp >> 1) * 32;
    int n_base = (warp & 1) * 64;
    int row0 = blockIdx.x * 128;

    float acc[2][8][4];
#pragma unroll
    for (int mt = 0; mt < 2; ++mt)
#pragma unroll
        for (int nt = 0; nt < 8; ++nt)
#pragma unroll
            for (int i = 0; i < 4; ++i) acc[mt][nt][i] = 0.f;

    dual_gemm_ca(out_, Wa, xtf_, Wb, smA, smB, row0, Nrows, tid,
                 m_base, n_base, g, tig, acc);

    const float2* x2 = reinterpret_cast<const float2*>(g_x);
#pragma unroll
    for (int nt = 0; nt < 8; ++nt) {
        int col = n_base + nt * 8 + 2 * tig;
        float2 bsum;
        bsum.x = __ldg(&ba[col])     + __ldg(&bb_[col]);
        bsum.y = __ldg(&ba[col + 1]) + __ldg(&bb_[col + 1]);
#pragma unroll
        for (int mt = 0; mt < 2; ++mt) {
#pragma unroll
            for (int h = 0; h < 2; ++h) {
                int row = row0 + m_base + mt * 16 + g + h * 8;
                if (row >= Nrows) continue;
                float sx = sigf(acc[mt][nt][2 * h]     + bsum.x);
                float sy = sigf(acc[mt][nt][2 * h + 1] + bsum.y);
                size_t p = (size_t)row * 64 + (col >> 1);
                if (mode == 0) {
                    reinterpret_cast<float2*>(g_z)[p] = make_float2(sx, sy);
                } else {
                    float2 xv = x2[p];
                    reinterpret_cast<float2*>(g_rx)[p] =
                        make_float2(rtf(sx * xv.x), rtf(sy * xv.y));
                }
            }
        }
    }
}

// Final gate: O = (1-z)*x + z*tanh(out@Wo1 + rx@Wo2 + bo1 + bo2)
__global__ void __launch_bounds__(THREADS, 2)
gate2_mma_kernel(const float* __restrict__ out_, const float* __restrict__ rx_,
                 const float* __restrict__ wtf,
                 const float* __restrict__ bo1, const float* __restrict__ bo2,
                 float* __restrict__ O, int Nrows)
{
    __shared__ float smA[2 * ABUF_F];
    __shared__ float smB[2 * BBUF_F];

    const float* Wa = wtf + (size_t)8 * D * D;
    const float* Wb = wtf + (size_t)9 * D * D;

    int tid  = threadIdx.x;
    int warp = tid >> 5;
    int lane = tid & 31;
    int g    = lane >> 2;
    int tig  = lane & 3;
    int m_base = (warp >> 1) * 32;
    int n_base = (warp & 1) * 64;
    int row0 = blockIdx.x * 128;

    float acc[2][8][4];
#pragma unroll
    for (int mt = 0; mt < 2; ++mt)
#pragma unroll
        for (int nt = 0; nt < 8; ++nt)
#pragma unroll
            for (int i = 0; i < 4; ++i) acc[mt][nt][i] = 0.f;

    dual_gemm_ca(out_, Wa, rx_, Wb, smA, smB, row0, Nrows, tid,
                 m_base, n_base, g, tig, acc);

    const float2* x2 = reinterpret_cast<const float2*>(g_x);
    const float2* z2 = reinterpret_cast<const float2*>(g_z);
#pragma unroll
    for (int nt = 0; nt < 8; ++nt) {
        int col = n_base + nt * 8 + 2 * tig;
        float2 bsum;
        bsum.x = __ldg(&bo1[col])     + __ldg(&bo2[col]);
        bsum.y = __ldg(&bo1[col + 1]) + __ldg(&bo2[col + 1]);
#pragma unroll
        for (int mt = 0; mt < 2; ++mt) {
#pragma unroll
            for (int h = 0; h < 2; ++h) {
                int row = row0 + m_base + mt * 16 + g + h * 8;
                if (row >= Nrows) continue;
                float tx = acc[mt][nt][2 * h]     + bsum.x;
                float ty = acc[mt][nt][2 * h + 1] + bsum.y;
                size_t p = (size_t)row * 64 + (col >> 1);
                float2 xv = x2[p];
                float2 zv = z2[p];
                float2 o;
                o.x = (1.f - zv.x) * xv.x + zv.x * tanhf(tx);
                o.y = (1.f - zv.y) * xv.y + zv.y * tanhf(ty);
                reinterpret_cast<float2*>(O)[p] = o;
            }
        }
    }
}

// ===========================================================================
// Conversions
// ===========================================================================
__global__ void cvtw_kernel(const float* w0, const float* w1, const float* w2,
                            const float* w3, const float* w4, const float* w5,
                            const float* w6, const float* w7, const float* w8,
                            const float* w9, float* dst)
{
    const float* ws[10] = {w0, w1, w2, w3, w4, w5, w6, w7, w8, w9};
    const float* w = ws[blockIdx.y];
    int i = blockIdx.x * 256 + threadIdx.x;
    dst[(size_t)blockIdx.y * D * D + i] = rtf(w[i]);
}

__global__ void cvtx_kernel(const float* __restrict__ src, float* __restrict__ dst, int n4)
{
    int i = blockIdx.x * blockDim.x + threadIdx.x;
    if (i < n4) {
        float4 v = reinterpret_cast<const float4*>(src)[i];
        reinterpret_cast<float4*>(dst)[i] =
            make_float4(rtf(v.x), rtf(v.y), rtf(v.z), rtf(v.w));
    }
}

// ===========================================================================
// CSR build + atomic-free aggregation
// ===========================================================================
__global__ void zero_cnt_kernel(int Nn)
{
    int i = blockIdx.x * blockDim.x + threadIdx.x;
    if (i < Nn) g_cnt[i] = 0;
}

__global__ void count_kernel(const int* __restrict__ rows, int E)
{
    int e = blockIdx.x * blockDim.x + threadIdx.x;
    if (e < E) atomicAdd(&g_cnt[rows[e]], 1);
}

__global__ void scan_kernel(int Nn)
{
    __shared__ int warp_tot[32];
    int t = threadIdx.x;
    int lane = t & 31, w = t >> 5;
    int C = (Nn + 1023) / 1024;
    int lo = t * C;
    int hi = min(lo + C, Nn);

    int sum = 0;
    for (int i = lo; i < hi; ++i) sum += g_cnt[i];

    int v = sum;
#pragma unroll
    for (int o = 1; o < 32; o <<= 1) {
        int u = __shfl_up_sync(0xffffffffu, v, o);
        if (lane >= o) v += u;
    }
    if (lane == 31) warp_tot[w] = v;
    __syncthreads();
    if (w == 0) {
        int tv = warp_tot[lane];
#pragma unroll
        for (int o = 1; o < 32; o <<= 1) {
            int u = __shfl_up_sync(0xffffffffu, tv, o);
            if (lane >= o) tv += u;
        }
        warp_tot[lane] = tv;
    }
    __syncthreads();
    int incl = v + (w > 0 ? warp_tot[w - 1] : 0);
    int run = incl - sum;

    for (int i = lo; i < hi; ++i) {
        int c = g_cnt[i];
        g_start[i] = run;
        g_cur[i] = run;
        run += c;
    }
    if (t == 1023) g_start[Nn] = run;
}

__global__ void fill_kernel(const int* __restrict__ rows, const int* __restrict__ cols,
                            const float* __restrict__ vals, int E)
{
    int e = blockIdx.x * blockDim.x + threadIdx.x;
    if (e < E) {
        int r = rows[e];
        int pos = atomicAdd(&g_cur[r], 1);
        g_edges[pos] = make_int2(cols[e], __float_as_int(vals[e]));
    }
}

// Warp per node; fp16 gather; 4 edges in flight (MLP=4).
__global__ void agg_kernel(const __half* __restrict__ xh, float* __restrict__ agg, int Nn)
{
    int gw = (blockIdx.x * blockDim.x + threadIdx.x) >> 5;
    int lane = threadIdx.x & 31;
    if (gw >= Nn) return;

    int s = __ldg(&g_start[gw]);
    int t = __ldg(&g_start[gw + 1]);
    const uint2* x2 = reinterpret_cast<const uint2*>(xh);

    float4 acc = make_float4(0.f, 0.f, 0.f, 0.f);
    int j = s;
    for (; j + 4 <= t; j += 4) {
        int2 e0 = __ldg(&g_edges[j]);
        int2 e1 = __ldg(&g_edges[j + 1]);
        int2 e2 = __ldg(&g_edges[j + 2]);
        int2 e3 = __ldg(&g_edges[j + 3]);
        uint2 u0 = x2[(size_t)e0.x * 32 + lane];
        uint2 u1 = x2[(size_t)e1.x * 32 + lane];
        uint2 u2 = x2[(size_t)e2.x * 32 + lane];
        uint2 u3 = x2[(size_t)e3.x * 32 + lane];
        float v0 = __int_as_float(e0.y);
        float v1 = __int_as_float(e1.y);
        float v2 = __int_as_float(e2.y);
        float v3 = __int_as_float(e3.y);
        {
            float2 a = __half22float2(*reinterpret_cast<__half2*>(&u0.x));
            float2 b = __half22float2(*reinterpret_cast<__half2*>(&u0.y));
            acc.x += v0 * a.x; acc.y += v0 * a.y; acc.z += v0 * b.x; acc.w += v0 * b.y;
        }
        {
            float2 a = __half22float2(*reinterpret_cast<__half2*>(&u1.x));
            float2 b = __half22float2(*reinterpret_cast<__half2*>(&u1.y));
            acc.x += v1 * a.x; acc.y += v1 * a.y; acc.z += v1 * b.x; acc.w += v1 * b.y;
        }
        {
            float2 a = __half22float2(*reinterpret_cast<__half2*>(&u2.x));
            float2 b = __half22float2(*reinterpret_cast<__half2*>(&u2.y));
            acc.x += v2 * a.x; acc.y += v2 * a.y; acc.z += v2 * b.x; acc.w += v2 * b.y;
        }
        {
            float2 a = __half22float2(*reinterpret_cast<__half2*>(&u3.x));
            float2 b = __half22float2(*reinterpret_cast<__half2*>(&u3.y));
            acc.x += v3 * a.x; acc.y += v3 * a.y; acc.z += v3 * b.x; acc.w += v3 * b.y;
        }
    }
    for (; j < t; ++j) {
        int2 ea = __ldg(&g_edges[j]);
        uint2 ua = x2[(size_t)ea.x * 32 + lane];
        float va = __int_as_float(ea.y);
        float2 a = __half22float2(*reinterpret_cast<__half2*>(&ua.x));
        float2 b = __half22float2(*reinterpret_cast<__half2*>(&ua.y));
        acc.x += va * a.x; acc.y += va * a.y; acc.z += va * b.x; acc.w += va * b.y;
    }
    reinterpret_cast<float4*>(agg)[(size_t)gw * D4 + lane] =
        make_float4(rtf(acc.x), rtf(acc.y), rtf(acc.z), rtf(acc.w));
}

// ---------------------------------------------------------------------------
extern "C" void kernel_launch(void* const* d_in, const int* in_sizes, int n_in,
                              void* d_out, int out_size)
{
    const float* x_in  = (const float*)d_in[0];
    const int*   rows  = (const int*)  d_in[1];
    const int*   cols  = (const int*)  d_in[2];
    const float* vals  = (const float*)d_in[3];
    const float* m1_W1 = (const float*)d_in[4];
    const float* m1_b1 = (const float*)d_in[5];
    const float* m1_W2 = (const float*)d_in[6];
    const float* m1_b2 = (const float*)d_in[7];
    const float* m2_W1 = (const float*)d_in[8];
    const float* m2_b1 = (const float*)d_in[9];
    const float* m2_W2 = (const float*)d_in[10];
    const float* m2_b2 = (const float*)d_in[11];
    const float* Wu1   = (const float*)d_in[12];
    const float* bu1   = (const float*)d_in[13];
    const float* Wu2   = (const float*)d_in[14];
    const float* bu2   = (const float*)d_in[15];
    const float* Wr1   = (const float*)d_in[16];
    const float* br1   = (const float*)d_in[17];
    const float* Wr2   = (const float*)d_in[18];
    const float* br2   = (const float*)d_in[19];
    const float* Wo1   = (const float*)d_in[20];
    const float* bo1   = (const float*)d_in[21];
    const float* Wo2   = (const float*)d_in[22];
    const float* bo2   = (const float*)d_in[23];

    int N = in_sizes[0] / D;
    int E = in_sizes[1];

    float *px, *pxtf, *pxin, *pagg, *pout, *prx, *pwtf;
    __half* pxh;
    cudaGetSymbolAddress((void**)&px,   g_x);
    cudaGetSymbolAddress((void**)&pxtf, g_xtf);
    cudaGetSymbolAddress((void**)&pxh,  g_xh);
    cudaGetSymbolAddress((void**)&pxin, g_xin);
    cudaGetSymbolAddress((void**)&pagg, g_agg);
    cudaGetSymbolAddress((void**)&pout, g_out);
    cudaGetSymbolAddress((void**)&prx,  g_rx);
    cudaGetSymbolAddress((void**)&pwtf, g_wtf);

    static cudaStream_t s_side = nullptr;
    static cudaEvent_t ev_fork = nullptr, ev_join = nullptr;
    if (!s_side) {
        cudaStreamCreateWithFlags(&s_side, cudaStreamNonBlocking);
        cudaEventCreateWithFlags(&ev_fork, cudaEventDisableTiming);
        cudaEventCreateWithFlags(&ev_join, cudaEventDisableTiming);
    }

    int smem_big = (2 * ABUF_F + 2 * BBUF_F + 128 * SB) * (int)sizeof(float);  // 107520 B
    cudaFuncSetAttribute(mlp2_mma_kernel<true>,  cudaFuncAttributeMaxDynamicSharedMemorySize, smem_big);
    cudaFuncSetAttribute(mlp2_mma_kernel<false>, cudaFuncAttributeMaxDynamicSharedMemorySize, smem_big);

    int nblk = (N + 127) / 128;
    int eblk = (E + 255) / 256;
    int n4 = N * D / 4;

    // ---- fork: CSR build on side stream ----
    cudaEventRecord(ev_fork, 0);
    cudaStreamWaitEvent(s_side, ev_fork, 0);
    zero_cnt_kernel<<<(N + 255) / 256, 256, 0, s_side>>>(N);
    count_kernel<<<eblk, 256, 0, s_side>>>(rows, E);
    scan_kernel<<<1, 1024, 0, s_side>>>(N);
    fill_kernel<<<eblk, 256, 0, s_side>>>(rows, cols, vals, E);
    cudaEventRecord(ev_join, s_side);

    // ---- main: conversions, then pipeline ----
    dim3 wgrid(64, 10);
    cvtw_kernel<<<wgrid, 256>>>(m1_W1, m1_W2, m2_W1, m2_W2, Wu1, Wu2, Wr1, Wr2, Wo1, Wo2, pwtf);
    cvtx_kernel<<<(n4 + 255) / 256, 256>>>(x_in, pxin, n4);

    mlp2_mma_kernel<true><<<nblk, THREADS, smem_big>>>(
        pxin, pwtf + 0 * D * D, m1_b1, pwtf + 1 * D * D, m1_b2, px, pxtf, pxh, N);

    cudaStreamWaitEvent(0, ev_join, 0);
    agg_kernel<<<(N * 32 + 255) / 256, 256>>>(pxh, pagg, N);

    mlp2_mma_kernel<false><<<nblk, THREADS, smem_big>>>(
        pagg, pwtf + 2 * D * D, m2_b1, pwtf + 3 * D * D, m2_b2, pout, nullptr, nullptr, N);

    dim3 grid01(nblk, 2);
    gate01_mma_kernel<<<grid01, THREADS>>>(pout, pxtf, pwtf, bu1, bu2, br1, br2, N);
    gate2_mma_kernel<<<nblk, THREADS>>>(pout, prx, pwtf, bo1, bo2, (float*)d_out, N);
}

// round 11
// speedup vs baseline: 1.3319x; 1.2320x over previous
#include <cuda_runtime.h>
#include <cuda_fp16.h>
#include <math.h>
#include <stdint.h>

#define D     128
#define NMAX  50000
#define EMAX  1600000
#define THREADS 256
#define BK2   32     // K per chunk (2 x k16 mma steps)
#define SAH   40     // A/B chunk smem stride in halves: (g*20+tig)%32 bijective
#define SHH   136    // Hs smem stride in halves: (g*4+tig)%32 bijective
#define ABUF_H (128 * SAH)   // 5120 halves = 10240 B
#define BBUF_H (128 * SAH)   // 5120 halves

// -------- device scratch --------
__device__ float  g_x[NMAX * D];       // fp32 x (epilogue math)
__device__ __half g_xh[NMAX * D];      // fp16 x (agg gather + gate A input)
__device__ __half g_xinh[NMAX * D];    // fp16 x_in
__device__ __half g_aggh[NMAX * D];    // fp16 agg
__device__ __half g_outh[NMAX * D];    // fp16 out
__device__ float  g_z[NMAX * D];       // fp32 z
__device__ __half g_rxh[NMAX * D];     // fp16 r*x
__device__ __half g_wh[10 * D * D];    // fp16 weights, TRANSPOSED [n][k]
__device__ int    g_cnt[NMAX];
__device__ int    g_start[NMAX + 1];
__device__ int    g_cur[NMAX];
__device__ int2   g_edges[EMAX];

__device__ __forceinline__ float sigf(float x) { return 1.0f / (1.0f + expf(-x)); }

__device__ __forceinline__ void mma_f16(float c[4],
                                        uint32_t a0, uint32_t a1, uint32_t a2, uint32_t a3,
                                        uint32_t b0, uint32_t b1) {
    asm volatile(
        "mma.sync.aligned.m16n8k16.row.col.f32.f16.f16.f32 "
        "{%0,%1,%2,%3}, {%4,%5,%6,%7}, {%8,%9}, {%0,%1,%2,%3};"
        : "+f"(c[0]), "+f"(c[1]), "+f"(c[2]), "+f"(c[3])
        : "r"(a0), "r"(a1), "r"(a2), "r"(a3), "r"(b0), "r"(b1));
}

// ---- cp.async helpers ----
__device__ __forceinline__ void cp16(void* dst_smem, const void* src, bool pred) {
    uint32_t dst = (uint32_t)__cvta_generic_to_shared(dst_smem);
    int sz = pred ? 16 : 0;
    asm volatile("cp.async.ca.shared.global [%0], [%1], 16, %2;\n"
                 :: "r"(dst), "l"(src), "r"(sz));
}
__device__ __forceinline__ void cp_commit() {
    asm volatile("cp.async.commit_group;\n");
}
template <int N>
__device__ __forceinline__ void cp_wait() {
    asm volatile("cp.async.wait_group %0;\n" :: "n"(N));
}

// A chunk [row0..+128) x [k0..+32) halves -> Abuf[row][k], stride SAH
__device__ __forceinline__ void cpA16(const __half* __restrict__ A, int row0, int Nrows,
                                      int k0, __half* Abuf, int tid) {
#pragma unroll
    for (int q2 = 0; q2 < 2; ++q2) {
        int idx = tid + q2 * 256;        // 0..511
        int row = idx >> 2;              // 0..127
        int q   = idx & 3;               // 16B = 8 halves each
        cp16(Abuf + row * SAH + q * 8,
             A + (size_t)(row0 + row) * D + k0 + q * 8,
             row0 + row < Nrows);
    }
}

// W chunk (transposed weights [n][k]) [0..128)n x [k0..+32) -> Bbuf[n][k], stride SAH
__device__ __forceinline__ void cpB16(const __half* __restrict__ Wt, int k0,
                                      __half* Bbuf, int tid) {
#pragma unroll
    for (int q2 = 0; q2 < 2; ++q2) {
        int idx = tid + q2 * 256;
        int n = idx >> 2;
        int q = idx & 3;
        cp16(Bbuf + n * SAH + q * 8, Wt + (size_t)n * D + k0 + q * 8, true);
    }
}

// ---- mma over one 32-k chunk (2 x k16); A row-major stride sa, base k offset ak0 ----
__device__ __forceinline__ void mma_chunk16(const __half* Ar, int sa, int ak0,
                                            const __half* Bs,
                                            int m_base, int n_base, int g, int tig,
                                            float acc[2][8][4]) {
#pragma unroll
    for (int ks = 0; ks < 2; ++ks) {
        int ka = ak0 + ks * 16 + 2 * tig;
        int kb = ks * 16 + 2 * tig;
        uint32_t afr[2][4];
#pragma unroll
        for (int mt = 0; mt < 2; ++mt) {
            const __half* p0 = Ar + (m_base + mt * 16 + g) * sa + ka;
            const __half* p1 = p0 + 8 * sa;
            afr[mt][0] = *reinterpret_cast<const uint32_t*>(p0);
            afr[mt][1] = *reinterpret_cast<const uint32_t*>(p1);
            afr[mt][2] = *reinterpret_cast<const uint32_t*>(p0 + 8);
            afr[mt][3] = *reinterpret_cast<const uint32_t*>(p1 + 8);
        }
#pragma unroll
        for (int nt = 0; nt < 8; ++nt) {
            const __half* pb = Bs + (n_base + nt * 8 + g) * SAH + kb;
            uint32_t b0 = *reinterpret_cast<const uint32_t*>(pb);
            uint32_t b1 = *reinterpret_cast<const uint32_t*>(pb + 8);
            mma_f16(acc[0][nt], afr[0][0], afr[0][1], afr[0][2], afr[0][3], b0, b1);
            mma_f16(acc[1][nt], afr[1][0], afr[1][1], afr[1][2], afr[1][3], b0, b1);
        }
    }
}

// Dual-GEMM accumulate, fp16, 2-stage cp.async (8 chunks of 32 k).
__device__ __forceinline__ void dual_gemm_h(const __half* A1, const __half* W1t,
                                            const __half* A2, const __half* W2t,
                                            __half* smA, __half* smB,
                                            int row0, int Nrows, int tid,
                                            int m_base, int n_base, int g, int tig,
                                            float acc[2][8][4]) {
    const __half* Aarr[2] = {A1, A2};
    const __half* Warr[2] = {W1t, W2t};
    __half* Ab[2] = {smA, smA + ABUF_H};
    __half* Bb[2] = {smB, smB + BBUF_H};

    cpA16(Aarr[0], row0, Nrows, 0, Ab[0], tid);
    cpB16(Warr[0], 0, Bb[0], tid);
    cp_commit();
#pragma unroll 1
    for (int t = 0; t < 8; ++t) {
        if (t < 7) {
            int tp = t + 1;
            cpA16(Aarr[tp >> 2], row0, Nrows, (tp & 3) * BK2, Ab[tp & 1], tid);
            cpB16(Warr[tp >> 2], (tp & 3) * BK2, Bb[tp & 1], tid);
            cp_commit();
            cp_wait<1>();
        } else {
            cp_wait<0>();
        }
        __syncthreads();
        mma_chunk16(Ab[t & 1], SAH, 0, Bb[t & 1], m_base, n_base, g, tig, acc);
        __syncthreads();
    }
}

// ===========================================================================
// Fused 2-layer MLP, fp16 tensor cores, cp.async 2-stage.
// DUAL: write fp32 to O and fp16 to OH; else fp16 to OH only.
// ===========================================================================
template <bool DUAL>
__global__ void __launch_bounds__(THREADS, 2)
mlp2_mma_kernel(const __half* __restrict__ A,
                const __half* __restrict__ W1t, const float* __restrict__ b1,
                const __half* __restrict__ W2t, const float* __restrict__ b2,
                float* __restrict__ O, __half* __restrict__ OH, int Nrows)
{
    extern __shared__ __half smh[];
    __half* Ab[2] = {smh, smh + ABUF_H};
    __half* Bb[2] = {smh + 2 * ABUF_H, smh + 2 * ABUF_H + BBUF_H};
    __half* Hs = smh + 2 * ABUF_H + 2 * BBUF_H;   // 128*SHH halves

    int tid  = threadIdx.x;
    int warp = tid >> 5;
    int lane = tid & 31;
    int g    = lane >> 2;
    int tig  = lane & 3;
    int m_base = (warp >> 1) * 32;
    int n_base = (warp & 1) * 64;
    int row0 = blockIdx.x * 128;

    float acc[2][8][4];
#pragma unroll
    for (int mt = 0; mt < 2; ++mt)
#pragma unroll
        for (int nt = 0; nt < 8; ++nt)
#pragma unroll
            for (int i = 0; i < 4; ++i) acc[mt][nt][i] = 0.f;

    // ---- layer 1: A @ W1 (4 chunks, A+B 2-stage) ----
    cpA16(A, row0, Nrows, 0, Ab[0], tid);
    cpB16(W1t, 0, Bb[0], tid);
    cp_commit();
#pragma unroll 1
    for (int kc = 0; kc < 4; ++kc) {
        if (kc < 3) {
            cpA16(A, row0, Nrows, (kc + 1) * BK2, Ab[(kc + 1) & 1], tid);
            cpB16(W1t, (kc + 1) * BK2, Bb[(kc + 1) & 1], tid);
            cp_commit();
            cp_wait<1>();
        } else {
            cp_wait<0>();
        }
        __syncthreads();
        mma_chunk16(Ab[kc & 1], SAH, 0, Bb[kc & 1], m_base, n_base, g, tig, acc);
        __syncthreads();
    }

    // prefetch W2 chunk0 (Bb[0] free)
    cpB16(W2t, 0, Bb[0], tid);
    cp_commit();

    // ---- epilogue 1: relu(acc + b1) -> Hs[row][col] fp16 ----
#pragma unroll
    for (int nt = 0; nt < 8; ++nt) {
        int col = n_base + nt * 8 + 2 * tig;
        float bx = __ldg(&b1[col]);
        float by = __ldg(&b1[col + 1]);
#pragma unroll
        for (int mt = 0; mt < 2; ++mt) {
#pragma unroll
            for (int h = 0; h < 2; ++h) {
                int row = m_base + mt * 16 + g + h * 8;
                float tx = fmaxf(acc[mt][nt][2 * h]     + bx, 0.f);
                float ty = fmaxf(acc[mt][nt][2 * h + 1] + by, 0.f);
                *reinterpret_cast<__half2*>(Hs + row * SHH + col) =
                    __float22half2_rn(make_float2(tx, ty));
                acc[mt][nt][2 * h] = 0.f;
                acc[mt][nt][2 * h + 1] = 0.f;
            }
        }
    }
    __syncthreads();

    // ---- layer 2: Hs @ W2 (4 chunks, B-only 2-stage) ----
#pragma unroll 1
    for (int kc = 0; kc < 4; ++kc) {
        if (kc < 3) {
            cpB16(W2t, (kc + 1) * BK2, Bb[(kc + 1) & 1], tid);
            cp_commit();
            cp_wait<1>();
        } else {
            cp_wait<0>();
        }
        __syncthreads();
        mma_chunk16(Hs, SHH, kc * BK2, Bb[kc & 1], m_base, n_base, g, tig, acc);
        __syncthreads();
    }

    // ---- epilogue 2 ----
#pragma unroll
    for (int nt = 0; nt < 8; ++nt) {
        int col = n_base + nt * 8 + 2 * tig;
        float2 bb = make_float2(__ldg(&b2[col]), __ldg(&b2[col + 1]));
#pragma unroll
        for (int mt = 0; mt < 2; ++mt) {
#pragma unroll
            for (int h = 0; h < 2; ++h) {
                int row = row0 + m_base + mt * 16 + g + h * 8;
                if (row >= Nrows) continue;
                float vx = acc[mt][nt][2 * h]     + bb.x;
                float vy = acc[mt][nt][2 * h + 1] + bb.y;
                if (DUAL)
                    *reinterpret_cast<float2*>(&O[(size_t)row * D + col]) =
                        make_float2(vx, vy);
                *reinterpret_cast<__half2*>(&OH[(size_t)row * D + col]) =
                    __float22half2_rn(make_float2(vx, vy));
            }
        }
    }
}

// ===========================================================================
// Merged z/r gate kernel (gridDim.y = 2), fp16 GEMMs.
// ===========================================================================
__global__ void __launch_bounds__(THREADS, 2)
gate01_mma_kernel(const __half* __restrict__ out_, const __half* __restrict__ xh_,
                  const __half* __restrict__ wh,
                  const float* __restrict__ bu1, const float* __restrict__ bu2,
                  const float* __restrict__ br1, const float* __restrict__ br2,
                  int Nrows)
{
    __shared__ __half smA[2 * ABUF_H];
    __shared__ __half smB[2 * BBUF_H];

    int mode = blockIdx.y;
    const __half* Wa = wh + (size_t)(4 + 2 * mode) * D * D;
    const __half* Wb = wh + (size_t)(5 + 2 * mode) * D * D;
    const float* ba = mode ? br1 : bu1;
    const float* bb_ = mode ? br2 : bu2;

    int tid  = threadIdx.x;
    int warp = tid >> 5;
    int lane = tid & 31;
    int g    = lane >> 2;
    int tig  = lane & 3;
    int m_base = (warp >> 1) * 32;
    int n_base = (warp & 1) * 64;
    int row0 = blockIdx.x * 128;

    float acc[2][8][4];
#pragma unroll
    for (int mt = 0; mt < 2; ++mt)
#pragma unroll
        for (int nt = 0; nt < 8; ++nt)
#pragma unroll
            for (int i = 0; i < 4; ++i) acc[mt][nt][i] = 0.f;

    dual_gemm_h(out_, Wa, xh_, Wb, smA, smB, row0, Nrows, tid,
                m_base, n_base, g, tig, acc);

    const float2* x2 = reinterpret_cast<const float2*>(g_x);
#pragma unroll
    for (int nt = 0; nt < 8; ++nt) {
        int col = n_base + nt * 8 + 2 * tig;
        float2 bsum;
        bsum.x = __ldg(&ba[col])     + __ldg(&bb_[col]);
        bsum.y = __ldg(&ba[col + 1]) + __ldg(&bb_[col + 1]);
#pragma unroll
        for (int mt = 0; mt < 2; ++mt) {
#pragma unroll
            for (int h = 0; h < 2; ++h) {
                int row = row0 + m_base + mt * 16 + g + h * 8;
                if (row >= Nrows) continue;
                float sx = sigf(acc[mt][nt][2 * h]     + bsum.x);
                float sy = sigf(acc[mt][nt][2 * h + 1] + bsum.y);
                size_t p = (size_t)row * 64 + (col >> 1);
                if (mode == 0) {
                    reinterpret_cast<float2*>(g_z)[p] = make_float2(sx, sy);
                } else {
                    float2 xv = x2[p];
                    *reinterpret_cast<__half2*>(&g_rxh[(size_t)row * D + col]) =
                        __float22half2_rn(make_float2(sx * xv.x, sy * xv.y));
                }
            }
        }
    }
}

// Final gate: O = (1-z)*x + z*tanh(out@Wo1 + rx@Wo2 + bo1 + bo2)
__global__ void __launch_bounds__(THREADS, 2)
gate2_mma_kernel(const __half* __restrict__ out_, const __half* __restrict__ rx_,
                 const __half* __restrict__ wh,
                 const float* __restrict__ bo1, const float* __restrict__ bo2,
                 float* __restrict__ O, int Nrows)
{
    __shared__ __half smA[2 * ABUF_H];
    __shared__ __half smB[2 * BBUF_H];

    const __half* Wa = wh + (size_t)8 * D * D;
    const __half* Wb = wh + (size_t)9 * D * D;

    int tid  = threadIdx.x;
    int warp = tid >> 5;
    int lane = tid & 31;
    int g    = lane >> 2;
    int tig  = lane & 3;
    int m_base = (warp >> 1) * 32;
    int n_base = (warp & 1) * 64;
    int row0 = blockIdx.x * 128;

    float acc[2][8][4];
#pragma unroll
    for (int mt = 0; mt < 2; ++mt)
#pragma unroll
        for (int nt = 0; nt < 8; ++nt)
#pragma unroll
            for (int i = 0; i < 4; ++i) acc[mt][nt][i] = 0.f;

    dual_gemm_h(out_, Wa, rx_, Wb, smA, smB, row0, Nrows, tid,
                m_base, n_base, g, tig, acc);

    const float2* x2 = reinterpret_cast<const float2*>(g_x);
    const float2* z2 = reinterpret_cast<const float2*>(g_z);
#pragma unroll
    for (int nt = 0; nt < 8; ++nt) {
        int col = n_base + nt * 8 + 2 * tig;
        float2 bsum;
        bsum.x = __ldg(&bo1[col])     + __ldg(&bo2[col]);
        bsum.y = __ldg(&bo1[col + 1]) + __ldg(&bo2[col + 1]);
#pragma unroll
        for (int mt = 0; mt < 2; ++mt) {
#pragma unroll
            for (int h = 0; h < 2; ++h) {
                int row = row0 + m_base + mt * 16 + g + h * 8;
                if (row >= Nrows) continue;
                float tx = acc[mt][nt][2 * h]     + bsum.x;
                float ty = acc[mt][nt][2 * h + 1] + bsum.y;
                size_t p = (size_t)row * 64 + (col >> 1);
                float2 xv = x2[p];
                float2 zv = z2[p];
                float2 o;
                o.x = (1.f - zv.x) * xv.x + zv.x * tanhf(tx);
                o.y = (1.f - zv.y) * xv.y + zv.y * tanhf(ty);
                reinterpret_cast<float2*>(O)[p] = o;
            }
        }
    }
}

// ===========================================================================
// Conversions: weights -> fp16 TRANSPOSED [n][k]; x_in -> fp16
// ===========================================================================
__global__ void cvtw_kernel(const float* w0, const float* w1, const float* w2,
                            const float* w3, const float* w4, const float* w5,
                            const float* w6, const float* w7, const float* w8,
                            const float* w9, __half* dst)
{
    const float* ws[10] = {w0, w1, w2, w3, w4, w5, w6, w7, w8, w9};
    const float* w = ws[blockIdx.y];
    int i = blockIdx.x * 256 + threadIdx.x;   // 16384 elems
    int n = i >> 7;
    int k = i & 127;
    dst[(size_t)blockIdx.y * D * D + i] = __float2half_rn(w[(size_t)k * D + n]);
}

__global__ void cvtx_kernel(const float* __restrict__ src, __half* __restrict__ dst, int n4)
{
    int i = blockIdx.x * blockDim.x + threadIdx.x;
    if (i < n4) {
        float4 v = reinterpret_cast<const float4*>(src)[i];
        __half2 h0 = __float22half2_rn(make_float2(v.x, v.y));
        __half2 h1 = __float22half2_rn(make_float2(v.z, v.w));
        reinterpret_cast<uint2*>(dst)[i] = make_uint2(
            *reinterpret_cast<uint32_t*>(&h0), *reinterpret_cast<uint32_t*>(&h1));
    }
}

// ===========================================================================
// CSR build + atomic-free aggregation (R10-proven)
// ===========================================================================
__global__ void zero_cnt_kernel(int Nn)
{
    int i = blockIdx.x * blockDim.x + threadIdx.x;
    if (i < Nn) g_cnt[i] = 0;
}

__global__ void count_kernel(const int* __restrict__ rows, int E)
{
    int e = blockIdx.x * blockDim.x + threadIdx.x;
    if (e < E) atomicAdd(&g_cnt[rows[e]], 1);
}

__global__ void scan_kernel(int Nn)
{
    __shared__ int warp_tot[32];
    int t = threadIdx.x;
    int lane = t & 31, w = t >> 5;
    int C = (Nn + 1023) / 1024;
    int lo = t * C;
    int hi = min(lo + C, Nn);

    int sum = 0;
    for (int i = lo; i < hi; ++i) sum += g_cnt[i];

    int v = sum;
#pragma unroll
    for (int o = 1; o < 32; o <<= 1) {
        int u = __shfl_up_sync(0xffffffffu, v, o);
        if (lane >= o) v += u;
    }
    if (lane == 31) warp_tot[w] = v;
    __syncthreads();
    if (w == 0) {
        int tv = warp_tot[lane];
#pragma unroll
        for (int o = 1; o < 32; o <<= 1) {
            int u = __shfl_up_sync(0xffffffffu, tv, o);
            if (lane >= o) tv += u;
        }
        warp_tot[lane] = tv;
    }
    __syncthreads();
    int incl = v + (w > 0 ? warp_tot[w - 1] : 0);
    int run = incl - sum;

    for (int i = lo; i < hi; ++i) {
        int c = g_cnt[i];
        g_start[i] = run;
        g_cur[i] = run;
        run += c;
    }
    if (t == 1023) g_start[Nn] = run;
}

__global__ void fill_kernel(const int* __restrict__ rows, const int* __restrict__ cols,
                            const float* __restrict__ vals, int E)
{
    int e = blockIdx.x * blockDim.x + threadIdx.x;
    if (e < E) {
        int r = rows[e];
        int pos = atomicAdd(&g_cur[r], 1);
        g_edges[pos] = make_int2(cols[e], __float_as_int(vals[e]));
    }
}

// Warp per node; fp16 gather; 4 edges in flight; fp16 output.
__global__ void agg_kernel(const __half* __restrict__ xh, __half* __restrict__ aggh, int Nn)
{
    int gw = (blockIdx.x * blockDim.x + threadIdx.x) >> 5;
    int lane = threadIdx.x & 31;
    if (gw >= Nn) return;

    int s = __ldg(&g_start[gw]);
    int t = __ldg(&g_start[gw + 1]);
    const uint2* x2 = reinterpret_cast<const uint2*>(xh);

    float4 acc = make_float4(0.f, 0.f, 0.f, 0.f);
    int j = s;
    for (; j + 4 <= t; j += 4) {
        int2 e0 = __ldg(&g_edges[j]);
        int2 e1 = __ldg(&g_edges[j + 1]);
        int2 e2 = __ldg(&g_edges[j + 2]);
        int2 e3 = __ldg(&g_edges[j + 3]);
        uint2 u0 = x2[(size_t)e0.x * 32 + lane];
        uint2 u1 = x2[(size_t)e1.x * 32 + lane];
        uint2 u2 = x2[(size_t)e2.x * 32 + lane];
        uint2 u3 = x2[(size_t)e3.x * 32 + lane];
        float v0 = __int_as_float(e0.y);
        float v1 = __int_as_float(e1.y);
        float v2 = __int_as_float(e2.y);
        float v3 = __int_as_float(e3.y);
        {
            float2 a = __half22float2(*reinterpret_cast<__half2*>(&u0.x));
            float2 b = __half22float2(*reinterpret_cast<__half2*>(&u0.y));
            acc.x += v0 * a.x; acc.y += v0 * a.y; acc.z += v0 * b.x; acc.w += v0 * b.y;
        }
        {
            float2 a = __half22float2(*reinterpret_cast<__half2*>(&u1.x));
            float2 b = __half22float2(*reinterpret_cast<__half2*>(&u1.y));
            acc.x += v1 * a.x; acc.y += v1 * a.y; acc.z += v1 * b.x; acc.w += v1 * b.y;
        }
        {
            float2 a = __half22float2(*reinterpret_cast<__half2*>(&u2.x));
            float2 b = __half22float2(*reinterpret_cast<__half2*>(&u2.y));
            acc.x += v2 * a.x; acc.y += v2 * a.y; acc.z += v2 * b.x; acc.w += v2 * b.y;
        }
        {
            float2 a = __half22float2(*reinterpret_cast<__half2*>(&u3.x));
            float2 b = __half22float2(*reinterpret_cast<__half2*>(&u3.y));
            acc.x += v3 * a.x; acc.y += v3 * a.y; acc.z += v3 * b.x; acc.w += v3 * b.y;
        }
    }
    for (; j < t; ++j) {
        int2 ea = __ldg(&g_edges[j]);
        uint2 ua = x2[(size_t)ea.x * 32 + lane];
        float va = __int_as_float(ea.y);
        float2 a = __half22float2(*reinterpret_cast<__half2*>(&ua.x));
        float2 b = __half22float2(*reinterpret_cast<__half2*>(&ua.y));
        acc.x += va * a.x; acc.y += va * a.y; acc.z += va * b.x; acc.w += va * b.y;
    }
    __half2 h0 = __float22half2_rn(make_float2(acc.x, acc.y));
    __half2 h1 = __float22half2_rn(make_float2(acc.z, acc.w));
    reinterpret_cast<uint2*>(aggh)[(size_t)gw * 32 + lane] = make_uint2(
        *reinterpret_cast<uint32_t*>(&h0), *reinterpret_cast<uint32_t*>(&h1));
}

// ---------------------------------------------------------------------------
extern "C" void kernel_launch(void* const* d_in, const int* in_sizes, int n_in,
                              void* d_out, int out_size)
{
    const float* x_in  = (const float*)d_in[0];
    const int*   rows  = (const int*)  d_in[1];
    const int*   cols  = (const int*)  d_in[2];
    const float* vals  = (const float*)d_in[3];
    const float* m1_W1 = (const float*)d_in[4];
    const float* m1_b1 = (const float*)d_in[5];
    const float* m1_W2 = (const float*)d_in[6];
    const float* m1_b2 = (const float*)d_in[7];
    const float* m2_W1 = (const float*)d_in[8];
    const float* m2_b1 = (const float*)d_in[9];
    const float* m2_W2 = (const float*)d_in[10];
    const float* m2_b2 = (const float*)d_in[11];
    const float* Wu1   = (const float*)d_in[12];
    const float* bu1   = (const float*)d_in[13];
    const float* Wu2   = (const float*)d_in[14];
    const float* bu2   = (const float*)d_in[15];
    const float* Wr1   = (const float*)d_in[16];
    const float* br1   = (const float*)d_in[17];
    const float* Wr2   = (const float*)d_in[18];
    const float* br2   = (const float*)d_in[19];
    const float* Wo1   = (const float*)d_in[20];
    const float* bo1   = (const float*)d_in[21];
    const float* Wo2   = (const float*)d_in[22];
    const float* bo2   = (const float*)d_in[23];

    int N = in_sizes[0] / D;
    int E = in_sizes[1];

    float *px, *pz;
    __half *pxh, *pxinh, *paggh, *pouth, *prxh, *pwh;
    cudaGetSymbolAddress((void**)&px,    g_x);
    cudaGetSymbolAddress((void**)&pz,    g_z);
    cudaGetSymbolAddress((void**)&pxh,   g_xh);
    cudaGetSymbolAddress((void**)&pxinh, g_xinh);
    cudaGetSymbolAddress((void**)&paggh, g_aggh);
    cudaGetSymbolAddress((void**)&pouth, g_outh);
    cudaGetSymbolAddress((void**)&prxh,  g_rxh);
    cudaGetSymbolAddress((void**)&pwh,   g_wh);

    static cudaStream_t s_side = nullptr;
    static cudaEvent_t ev_fork = nullptr, ev_join = nullptr;
    if (!s_side) {
        cudaStreamCreateWithFlags(&s_side, cudaStreamNonBlocking);
        cudaEventCreateWithFlags(&ev_fork, cudaEventDisableTiming);
        cudaEventCreateWithFlags(&ev_join, cudaEventDisableTiming);
    }

    int smem_mlp = (2 * ABUF_H + 2 * BBUF_H + 128 * SHH) * (int)sizeof(__half);  // 75776 B
    cudaFuncSetAttribute(mlp2_mma_kernel<true>,  cudaFuncAttributeMaxDynamicSharedMemorySize, smem_mlp);
    cudaFuncSetAttribute(mlp2_mma_kernel<false>, cudaFuncAttributeMaxDynamicSharedMemorySize, smem_mlp);

    int nblk = (N + 127) / 128;
    int eblk = (E + 255) / 256;
    int n4 = N * D / 4;

    // ---- fork: CSR build on side stream ----
    cudaEventRecord(ev_fork, 0);
    cudaStreamWaitEvent(s_side, ev_fork, 0);
    zero_cnt_kernel<<<(N + 255) / 256, 256, 0, s_side>>>(N);
    count_kernel<<<eblk, 256, 0, s_side>>>(rows, E);
    scan_kernel<<<1, 1024, 0, s_side>>>(N);
    fill_kernel<<<eblk, 256, 0, s_side>>>(rows, cols, vals, E);
    cudaEventRecord(ev_join, s_side);

    // ---- main: conversions, then pipeline ----
    dim3 wgrid(64, 10);
    cvtw_kernel<<<wgrid, 256>>>(m1_W1, m1_W2, m2_W1, m2_W2, Wu1, Wu2, Wr1, Wr2, Wo1, Wo2, pwh);
    cvtx_kernel<<<(n4 + 255) / 256, 256>>>(x_in, pxinh, n4);

    mlp2_mma_kernel<true><<<nblk, THREADS, smem_mlp>>>(
        pxinh, pwh + 0 * D * D, m1_b1, pwh + 1 * D * D, m1_b2, px, pxh, N);

    cudaStreamWaitEvent(0, ev_join, 0);
    agg_kernel<<<(N * 32 + 255) / 256, 256>>>(pxh, paggh, N);

    mlp2_mma_kernel<false><<<nblk, THREADS, smem_mlp>>>(
        paggh, pwh + 2 * D * D, m2_b1, pwh + 3 * D * D, m2_b2, nullptr, pouth, N);

    dim3 grid01(nblk, 2);
    gate01_mma_kernel<<<grid01, THREADS>>>(pouth, pxh, pwh, bu1, bu2, br1, br2, N);
    gate2_mma_kernel<<<nblk, THREADS>>>(pouth, prxh, pwh, bo1, bo2, (float*)d_out, N);
}

// round 12
// speedup vs baseline: 1.3963x; 1.0484x over previous
#include <cuda_runtime.h>
#include <cuda_fp16.h>
#include <math.h>
#include <stdint.h>

#define D     128
#define NMAX  50000
#define EMAX  1600000
#define THREADS 256
#define BK2   64     // K per chunk (4 x k16 mma steps)
#define SAH   72     // A/B chunk smem stride in halves: (4g+tig)%32 bijective
#define SHH   136    // Hs smem stride in halves
#define ABUF_H (128 * SAH)   // 9216 halves = 18432 B
#define BBUF_H (128 * SAH)

// -------- device scratch --------
__device__ float  g_x[NMAX * D];       // fp32 x (epilogue math)
__device__ __half g_xh[NMAX * D];      // fp16 x (agg gather + gate A input)
__device__ __half g_xinh[NMAX * D];    // fp16 x_in
__device__ __half g_aggh[NMAX * D];    // fp16 agg
__device__ __half g_outh[NMAX * D];    // fp16 out
__device__ float  g_z[NMAX * D];       // fp32 z
__device__ __half g_rxh[NMAX * D];     // fp16 r*x
__device__ __half g_wh[10 * D * D];    // fp16 weights, TRANSPOSED [n][k]
__device__ int    g_cnt[NMAX];
__device__ int    g_start[NMAX + 1];
__device__ int    g_cur[NMAX];
__device__ int2   g_edges[EMAX];

__device__ __forceinline__ float sigf(float x) { return 1.0f / (1.0f + expf(-x)); }

__device__ __forceinline__ void mma_f16(float c[4],
                                        uint32_t a0, uint32_t a1, uint32_t a2, uint32_t a3,
                                        uint32_t b0, uint32_t b1) {
    asm volatile(
        "mma.sync.aligned.m16n8k16.row.col.f32.f16.f16.f32 "
        "{%0,%1,%2,%3}, {%4,%5,%6,%7}, {%8,%9}, {%0,%1,%2,%3};"
        : "+f"(c[0]), "+f"(c[1]), "+f"(c[2]), "+f"(c[3])
        : "r"(a0), "r"(a1), "r"(a2), "r"(a3), "r"(b0), "r"(b1));
}

// ---- cp.async helpers ----
__device__ __forceinline__ void cp16(void* dst_smem, const void* src, bool pred) {
    uint32_t dst = (uint32_t)__cvta_generic_to_shared(dst_smem);
    int sz = pred ? 16 : 0;
    asm volatile("cp.async.ca.shared.global [%0], [%1], 16, %2;\n"
                 :: "r"(dst), "l"(src), "r"(sz));
}
__device__ __forceinline__ void cp_commit() {
    asm volatile("cp.async.commit_group;\n");
}
template <int N>
__device__ __forceinline__ void cp_wait() {
    asm volatile("cp.async.wait_group %0;\n" :: "n"(N));
}

// A chunk [row0..+128) x [k0..+64) halves -> Abuf[row][k], stride SAH
__device__ __forceinline__ void cpA16(const __half* __restrict__ A, int row0, int Nrows,
                                      int k0, __half* Abuf, int tid) {
#pragma unroll
    for (int q2 = 0; q2 < 4; ++q2) {
        int idx = tid + q2 * 256;        // 0..1023
        int row = idx >> 3;              // 0..127
        int q   = idx & 7;               // 8 x 16B segments = 64 halves
        cp16(Abuf + row * SAH + q * 8,
             A + (size_t)(row0 + row) * D + k0 + q * 8,
             row0 + row < Nrows);
    }
}

// W chunk (transposed weights [n][k]) [0..128)n x [k0..+64) -> Bbuf[n][k]
__device__ __forceinline__ void cpB16(const __half* __restrict__ Wt, int k0,
                                      __half* Bbuf, int tid) {
#pragma unroll
    for (int q2 = 0; q2 < 4; ++q2) {
        int idx = tid + q2 * 256;
        int n = idx >> 3;
        int q = idx & 7;
        cp16(Bbuf + n * SAH + q * 8, Wt + (size_t)n * D + k0 + q * 8, true);
    }
}

// ---- mma over one 64-k chunk (4 x k16); A row-major stride sa, base k offset ak0 ----
__device__ __forceinline__ void mma_chunk16(const __half* Ar, int sa, int ak0,
                                            const __half* Bs,
                                            int m_base, int n_base, int g, int tig,
                                            float acc[2][8][4]) {
#pragma unroll
    for (int ks = 0; ks < 4; ++ks) {
        int ka = ak0 + ks * 16 + 2 * tig;
        int kb = ks * 16 + 2 * tig;
        uint32_t afr[2][4];
#pragma unroll
        for (int mt = 0; mt < 2; ++mt) {
            const __half* p0 = Ar + (m_base + mt * 16 + g) * sa + ka;
            const __half* p1 = p0 + 8 * sa;
            afr[mt][0] = *reinterpret_cast<const uint32_t*>(p0);
            afr[mt][1] = *reinterpret_cast<const uint32_t*>(p1);
            afr[mt][2] = *reinterpret_cast<const uint32_t*>(p0 + 8);
            afr[mt][3] = *reinterpret_cast<const uint32_t*>(p1 + 8);
        }
#pragma unroll
        for (int nt = 0; nt < 8; ++nt) {
            const __half* pb = Bs + (n_base + nt * 8 + g) * SAH + kb;
            uint32_t b0 = *reinterpret_cast<const uint32_t*>(pb);
            uint32_t b1 = *reinterpret_cast<const uint32_t*>(pb + 8);
            mma_f16(acc[0][nt], afr[0][0], afr[0][1], afr[0][2], afr[0][3], b0, b1);
            mma_f16(acc[1][nt], afr[1][0], afr[1][1], afr[1][2], afr[1][3], b0, b1);
        }
    }
}

// Dual-GEMM accumulate, fp16, 2-stage cp.async (4 chunks of 64 k).
__device__ __forceinline__ void dual_gemm_h(const __half* A1, const __half* W1t,
                                            const __half* A2, const __half* W2t,
                                            __half* smA, __half* smB,
                                            int row0, int Nrows, int tid,
                                            int m_base, int n_base, int g, int tig,
                                            float acc[2][8][4]) {
    const __half* Aarr[2] = {A1, A2};
    const __half* Warr[2] = {W1t, W2t};
    __half* Ab[2] = {smA, smA + ABUF_H};
    __half* Bb[2] = {smB, smB + BBUF_H};

    cpA16(Aarr[0], row0, Nrows, 0, Ab[0], tid);
    cpB16(Warr[0], 0, Bb[0], tid);
    cp_commit();
#pragma unroll 1
    for (int t = 0; t < 4; ++t) {
        if (t < 3) {
            int tp = t + 1;
            cpA16(Aarr[tp >> 1], row0, Nrows, (tp & 1) * BK2, Ab[tp & 1], tid);
            cpB16(Warr[tp >> 1], (tp & 1) * BK2, Bb[tp & 1], tid);
            cp_commit();
            cp_wait<1>();
        } else {
            cp_wait<0>();
        }
        __syncthreads();
        mma_chunk16(Ab[t & 1], SAH, 0, Bb[t & 1], m_base, n_base, g, tig, acc);
        __syncthreads();
    }
}

// ===========================================================================
// Fused 2-layer MLP, fp16 tensor cores, cp.async 2-stage, 64-k chunks.
// DUAL: write fp32 to O and fp16 to OH; else fp16 to OH only.
// ===========================================================================
template <bool DUAL>
__global__ void __launch_bounds__(THREADS, 2)
mlp2_mma_kernel(const __half* __restrict__ A,
                const __half* __restrict__ W1t, const float* __restrict__ b1,
                const __half* __restrict__ W2t, const float* __restrict__ b2,
                float* __restrict__ O, __half* __restrict__ OH, int Nrows)
{
    extern __shared__ __half smh[];
    __half* Ab[2] = {smh, smh + ABUF_H};
    __half* Bb[2] = {smh + 2 * ABUF_H, smh + 2 * ABUF_H + BBUF_H};
    __half* Hs = smh + 2 * ABUF_H + 2 * BBUF_H;   // 128*SHH halves

    int tid  = threadIdx.x;
    int warp = tid >> 5;
    int lane = tid & 31;
    int g    = lane >> 2;
    int tig  = lane & 3;
    int m_base = (warp >> 1) * 32;
    int n_base = (warp & 1) * 64;
    int row0 = blockIdx.x * 128;

    float acc[2][8][4];
#pragma unroll
    for (int mt = 0; mt < 2; ++mt)
#pragma unroll
        for (int nt = 0; nt < 8; ++nt)
#pragma unroll
            for (int i = 0; i < 4; ++i) acc[mt][nt][i] = 0.f;

    // ---- layer 1: A @ W1 (2 chunks, A+B 2-stage) ----
    cpA16(A, row0, Nrows, 0, Ab[0], tid);
    cpB16(W1t, 0, Bb[0], tid);
    cp_commit();
#pragma unroll 1
    for (int kc = 0; kc < 2; ++kc) {
        if (kc < 1) {
            cpA16(A, row0, Nrows, BK2, Ab[1], tid);
            cpB16(W1t, BK2, Bb[1], tid);
            cp_commit();
            cp_wait<1>();
        } else {
            cp_wait<0>();
        }
        __syncthreads();
        mma_chunk16(Ab[kc & 1], SAH, 0, Bb[kc & 1], m_base, n_base, g, tig, acc);
        __syncthreads();
    }

    // prefetch W2 chunk0 (Bb[0] free)
    cpB16(W2t, 0, Bb[0], tid);
    cp_commit();

    // ---- epilogue 1: relu(acc + b1) -> Hs[row][col] fp16 ----
#pragma unroll
    for (int nt = 0; nt < 8; ++nt) {
        int col = n_base + nt * 8 + 2 * tig;
        float bx = __ldg(&b1[col]);
        float by = __ldg(&b1[col + 1]);
#pragma unroll
        for (int mt = 0; mt < 2; ++mt) {
#pragma unroll
            for (int h = 0; h < 2; ++h) {
                int row = m_base + mt * 16 + g + h * 8;
                float tx = fmaxf(acc[mt][nt][2 * h]     + bx, 0.f);
                float ty = fmaxf(acc[mt][nt][2 * h + 1] + by, 0.f);
                *reinterpret_cast<__half2*>(Hs + row * SHH + col) =
                    __float22half2_rn(make_float2(tx, ty));
                acc[mt][nt][2 * h] = 0.f;
                acc[mt][nt][2 * h + 1] = 0.f;
            }
        }
    }
    __syncthreads();

    // ---- layer 2: Hs @ W2 (2 chunks, B-only 2-stage) ----
#pragma unroll 1
    for (int kc = 0; kc < 2; ++kc) {
        if (kc < 1) {
            cpB16(W2t, BK2, Bb[1], tid);
            cp_commit();
            cp_wait<1>();
        } else {
            cp_wait<0>();
        }
        __syncthreads();
        mma_chunk16(Hs, SHH, kc * BK2, Bb[kc & 1], m_base, n_base, g, tig, acc);
        __syncthreads();
    }

    // ---- epilogue 2 ----
#pragma unroll
    for (int nt = 0; nt < 8; ++nt) {
        int col = n_base + nt * 8 + 2 * tig;
        float2 bb = make_float2(__ldg(&b2[col]), __ldg(&b2[col + 1]));
#pragma unroll
        for (int mt = 0; mt < 2; ++mt) {
#pragma unroll
            for (int h = 0; h < 2; ++h) {
                int row = row0 + m_base + mt * 16 + g + h * 8;
                if (row >= Nrows) continue;
                float vx = acc[mt][nt][2 * h]     + bb.x;
                float vy = acc[mt][nt][2 * h + 1] + bb.y;
                if (DUAL)
                    *reinterpret_cast<float2*>(&O[(size_t)row * D + col]) =
                        make_float2(vx, vy);
                *reinterpret_cast<__half2*>(&OH[(size_t)row * D + col]) =
                    __float22half2_rn(make_float2(vx, vy));
            }
        }
    }
}

// ===========================================================================
// Merged z/r gate kernel (gridDim.y = 2), fp16 GEMMs.
// ===========================================================================
__global__ void __launch_bounds__(THREADS, 2)
gate01_mma_kernel(const __half* __restrict__ out_, const __half* __restrict__ xh_,
                  const __half* __restrict__ wh,
                  const float* __restrict__ bu1, const float* __restrict__ bu2,
                  const float* __restrict__ br1, const float* __restrict__ br2,
                  int Nrows)
{
    __shared__ __half smA[2 * ABUF_H];
    __shared__ __half smB[2 * BBUF_H];

    int mode = blockIdx.y;
    const __half* Wa = wh + (size_t)(4 + 2 * mode) * D * D;
    const __half* Wb = wh + (size_t)(5 + 2 * mode) * D * D;
    const float* ba = mode ? br1 : bu1;
    const float* bb_ = mode ? br2 : bu2;

    int tid  = threadIdx.x;
    int warp = tid >> 5;
    int lane = tid & 31;
    int g    = lane >> 2;
    int tig  = lane & 3;
    int m_base = (warp >> 1) * 32;
    int n_base = (warp & 1) * 64;
    int row0 = blockIdx.x * 128;

    float acc[2][8][4];
#pragma unroll
    for (int mt = 0; mt < 2; ++mt)
#pragma unroll
        for (int nt = 0; nt < 8; ++nt)
#pragma unroll
            for (int i = 0; i < 4; ++i) acc[mt][nt][i] = 0.f;

    dual_gemm_h(out_, Wa, xh_, Wb, smA, smB, row0, Nrows, tid,
                m_base, n_base, g, tig, acc);

    const float2* x2 = reinterpret_cast<const float2*>(g_x);
#pragma unroll
    for (int nt = 0; nt < 8; ++nt) {
        int col = n_base + nt * 8 + 2 * tig;
        float2 bsum;
        bsum.x = __ldg(&ba[col])     + __ldg(&bb_[col]);
        bsum.y = __ldg(&ba[col + 1]) + __ldg(&bb_[col + 1]);
#pragma unroll
        for (int mt = 0; mt < 2; ++mt) {
#pragma unroll
            for (int h = 0; h < 2; ++h) {
                int row = row0 + m_base + mt * 16 + g + h * 8;
                if (row >= Nrows) continue;
                float sx = sigf(acc[mt][nt][2 * h]     + bsum.x);
                float sy = sigf(acc[mt][nt][2 * h + 1] + bsum.y);
                size_t p = (size_t)row * 64 + (col >> 1);
                if (mode == 0) {
                    reinterpret_cast<float2*>(g_z)[p] = make_float2(sx, sy);
                } else {
                    float2 xv = x2[p];
                    *reinterpret_cast<__half2*>(&g_rxh[(size_t)row * D + col]) =
                        __float22half2_rn(make_float2(sx * xv.x, sy * xv.y));
                }
            }
        }
    }
}

// Final gate: O = (1-z)*x + z*tanh(out@Wo1 + rx@Wo2 + bo1 + bo2)
__global__ void __launch_bounds__(THREADS, 2)
gate2_mma_kernel(const __half* __restrict__ out_, const __half* __restrict__ rx_,
                 const __half* __restrict__ wh,
                 const float* __restrict__ bo1, const float* __restrict__ bo2,
                 float* __restrict__ O, int Nrows)
{
    __shared__ __half smA[2 * ABUF_H];
    __shared__ __half smB[2 * BBUF_H];

    const __half* Wa = wh + (size_t)8 * D * D;
    const __half* Wb = wh + (size_t)9 * D * D;

    int tid  = threadIdx.x;
    int warp = tid >> 5;
    int lane = tid & 31;
    int g    = lane >> 2;
    int tig  = lane & 3;
    int m_base = (warp >> 1) * 32;
    int n_base = (warp & 1) * 64;
    int row0 = blockIdx.x * 128;

    float acc[2][8][4];
#pragma unroll
    for (int mt = 0; mt < 2; ++mt)
#pragma unroll
        for (int nt = 0; nt < 8; ++nt)
#pragma unroll
            for (int i = 0; i < 4; ++i) acc[mt][nt][i] = 0.f;

    dual_gemm_h(out_, Wa, rx_, Wb, smA, smB, row0, Nrows, tid,
                m_base, n_base, g, tig, acc);

    const float2* x2 = reinterpret_cast<const float2*>(g_x);
    const float2* z2 = reinterpret_cast<const float2*>(g_z);
#pragma unroll
    for (int nt = 0; nt < 8; ++nt) {
        int col = n_base + nt * 8 + 2 * tig;
        float2 bsum;
        bsum.x = __ldg(&bo1[col])     + __ldg(&bo2[col]);
        bsum.y = __ldg(&bo1[col + 1]) + __ldg(&bo2[col + 1]);
#pragma unroll
        for (int mt = 0; mt < 2; ++mt) {
#pragma unroll
            for (int h = 0; h < 2; ++h) {
                int row = row0 + m_base + mt * 16 + g + h * 8;
                if (row >= Nrows) continue;
                float tx = acc[mt][nt][2 * h]     + bsum.x;
                float ty = acc[mt][nt][2 * h + 1] + bsum.y;
                size_t p = (size_t)row * 64 + (col >> 1);
                float2 xv = x2[p];
                float2 zv = z2[p];
                float2 o;
                o.x = (1.f - zv.x) * xv.x + zv.x * tanhf(tx);
                o.y = (1.f - zv.y) * xv.y + zv.y * tanhf(ty);
                reinterpret_cast<float2*>(O)[p] = o;
            }
        }
    }
}

// ===========================================================================
// Conversions: weights -> fp16 TRANSPOSED [n][k]; x_in -> fp16
// ===========================================================================
__global__ void cvtw_kernel(const float* w0, const float* w1, const float* w2,
                            const float* w3, const float* w4, const float* w5,
                            const float* w6, const float* w7, const float* w8,
                            const float* w9, __half* dst)
{
    const float* ws[10] = {w0, w1, w2, w3, w4, w5, w6, w7, w8, w9};
    const float* w = ws[blockIdx.y];
    int i = blockIdx.x * 256 + threadIdx.x;   // 16384 elems
    int n = i >> 7;
    int k = i & 127;
    dst[(size_t)blockIdx.y * D * D + i] = __float2half_rn(w[(size_t)k * D + n]);
}

__global__ void cvtx_kernel(const float* __restrict__ src, __half* __restrict__ dst, int n4)
{
    int i = blockIdx.x * blockDim.x + threadIdx.x;
    if (i < n4) {
        float4 v = reinterpret_cast<const float4*>(src)[i];
        __half2 h0 = __float22half2_rn(make_float2(v.x, v.y));
        __half2 h1 = __float22half2_rn(make_float2(v.z, v.w));
        reinterpret_cast<uint2*>(dst)[i] = make_uint2(
            *reinterpret_cast<uint32_t*>(&h0), *reinterpret_cast<uint32_t*>(&h1));
    }
}

// ===========================================================================
// CSR build + atomic-free aggregation
// ===========================================================================
__global__ void zero_cnt_kernel(int Nn)
{
    int i = blockIdx.x * blockDim.x + threadIdx.x;
    if (i < Nn) g_cnt[i] = 0;
}

__global__ void count_kernel(const int* __restrict__ rows, int E)
{
    int e = blockIdx.x * blockDim.x + threadIdx.x;
    if (e < E) atomicAdd(&g_cnt[rows[e]], 1);
}

__global__ void scan_kernel(int Nn)
{
    __shared__ int warp_tot[32];
    int t = threadIdx.x;
    int lane = t & 31, w = t >> 5;
    int C = (Nn + 1023) / 1024;
    int lo = t * C;
    int hi = min(lo + C, Nn);

    int sum = 0;
    for (int i = lo; i < hi; ++i) sum += g_cnt[i];

    int v = sum;
#pragma unroll
    for (int o = 1; o < 32; o <<= 1) {
        int u = __shfl_up_sync(0xffffffffu, v, o);
        if (lane >= o) v += u;
    }
    if (lane == 31) warp_tot[w] = v;
    __syncthreads();
    if (w == 0) {
        int tv = warp_tot[lane];
#pragma unroll
        for (int o = 1; o < 32; o <<= 1) {
            int u = __shfl_up_sync(0xffffffffu, tv, o);
            if (lane >= o) tv += u;
        }
        warp_tot[lane] = tv;
    }
    __syncthreads();
    int incl = v + (w > 0 ? warp_tot[w - 1] : 0);
    int run = incl - sum;

    for (int i = lo; i < hi; ++i) {
        int c = g_cnt[i];
        g_start[i] = run;
        g_cur[i] = run;
        run += c;
    }
    if (t == 1023) g_start[Nn] = run;
}

__global__ void fill_kernel(const int* __restrict__ rows, const int* __restrict__ cols,
                            const float* __restrict__ vals, int E)
{
    int e = blockIdx.x * blockDim.x + threadIdx.x;
    if (e < E) {
        int r = rows[e];
        int pos = atomicAdd(&g_cur[r], 1);
        g_edges[pos] = make_int2(cols[e], __float_as_int(vals[e]));
    }
}

// Warp per node; fp16 gather; 8 edges in flight; fp16 output.
__global__ void agg_kernel(const __half* __restrict__ xh, __half* __restrict__ aggh, int Nn)
{
    int gw = (blockIdx.x * blockDim.x + threadIdx.x) >> 5;
    int lane = threadIdx.x & 31;
    if (gw >= Nn) return;

    int s = __ldg(&g_start[gw]);
    int t = __ldg(&g_start[gw + 1]);
    const uint2* x2 = reinterpret_cast<const uint2*>(xh);

    float4 acc = make_float4(0.f, 0.f, 0.f, 0.f);
    int j = s;
    for (; j + 8 <= t; j += 8) {
        int2 ee[8];
        uint2 uu[8];
#pragma unroll
        for (int q = 0; q < 8; ++q) ee[q] = __ldg(&g_edges[j + q]);
#pragma unroll
        for (int q = 0; q < 8; ++q) uu[q] = x2[(size_t)ee[q].x * 32 + lane];
#pragma unroll
        for (int q = 0; q < 8; ++q) {
            float v = __int_as_float(ee[q].y);
            float2 a = __half22float2(*reinterpret_cast<__half2*>(&uu[q].x));
            float2 b = __half22float2(*reinterpret_cast<__half2*>(&uu[q].y));
            acc.x += v * a.x; acc.y += v * a.y; acc.z += v * b.x; acc.w += v * b.y;
        }
    }
    for (; j < t; ++j) {
        int2 ea = __ldg(&g_edges[j]);
        uint2 ua = x2[(size_t)ea.x * 32 + lane];
        float va = __int_as_float(ea.y);
        float2 a = __half22float2(*reinterpret_cast<__half2*>(&ua.x));
        float2 b = __half22float2(*reinterpret_cast<__half2*>(&ua.y));
        acc.x += va * a.x; acc.y += va * a.y; acc.z += va * b.x; acc.w += va * b.y;
    }
    __half2 h0 = __float22half2_rn(make_float2(acc.x, acc.y));
    __half2 h1 = __float22half2_rn(make_float2(acc.z, acc.w));
    reinterpret_cast<uint2*>(aggh)[(size_t)gw * 32 + lane] = make_uint2(
        *reinterpret_cast<uint32_t*>(&h0), *reinterpret_cast<uint32_t*>(&h1));
}

// ---------------------------------------------------------------------------
extern "C" void kernel_launch(void* const* d_in, const int* in_sizes, int n_in,
                              void* d_out, int out_size)
{
    const float* x_in  = (const float*)d_in[0];
    const int*   rows  = (const int*)  d_in[1];
    const int*   cols  = (const int*)  d_in[2];
    const float* vals  = (const float*)d_in[3];
    const float* m1_W1 = (const float*)d_in[4];
    const float* m1_b1 = (const float*)d_in[5];
    const float* m1_W2 = (const float*)d_in[6];
    const float* m1_b2 = (const float*)d_in[7];
    const float* m2_W1 = (const float*)d_in[8];
    const float* m2_b1 = (const float*)d_in[9];
    const float* m2_W2 = (const float*)d_in[10];
    const float* m2_b2 = (const float*)d_in[11];
    const float* Wu1   = (const float*)d_in[12];
    const float* bu1   = (const float*)d_in[13];
    const float* Wu2   = (const float*)d_in[14];
    const float* bu2   = (const float*)d_in[15];
    const float* Wr1   = (const float*)d_in[16];
    const float* br1   = (const float*)d_in[17];
    const float* Wr2   = (const float*)d_in[18];
    const float* br2   = (const float*)d_in[19];
    const float* Wo1   = (const float*)d_in[20];
    const float* bo1   = (const float*)d_in[21];
    const float* Wo2   = (const float*)d_in[22];
    const float* bo2   = (const float*)d_in[23];

    int N = in_sizes[0] / D;
    int E = in_sizes[1];

    float *px;
    __half *pxh, *pxinh, *paggh, *pouth, *prxh, *pwh;
    cudaGetSymbolAddress((void**)&px,    g_x);
    cudaGetSymbolAddress((void**)&pxh,   g_xh);
    cudaGetSymbolAddress((void**)&pxinh, g_xinh);
    cudaGetSymbolAddress((void**)&paggh, g_aggh);
    cudaGetSymbolAddress((void**)&pouth, g_outh);
    cudaGetSymbolAddress((void**)&prxh,  g_rxh);
    cudaGetSymbolAddress((void**)&pwh,   g_wh);

    static cudaStream_t s_side = nullptr;
    static cudaEvent_t ev_fork = nullptr, ev_join = nullptr;
    if (!s_side) {
        cudaStreamCreateWithFlags(&s_side, cudaStreamNonBlocking);
        cudaEventCreateWithFlags(&ev_fork, cudaEventDisableTiming);
        cudaEventCreateWithFlags(&ev_join, cudaEventDisableTiming);
    }

    int smem_mlp = (2 * ABUF_H + 2 * BBUF_H + 128 * SHH) * (int)sizeof(__half);  // 108544 B
    cudaFuncSetAttribute(mlp2_mma_kernel<true>,  cudaFuncAttributeMaxDynamicSharedMemorySize, smem_mlp);
    cudaFuncSetAttribute(mlp2_mma_kernel<false>, cudaFuncAttributeMaxDynamicSharedMemorySize, smem_mlp);

    int nblk = (N + 127) / 128;
    int eblk = (E + 255) / 256;
    int n4 = N * D / 4;

    // ---- fork: CSR build on side stream ----
    cudaEventRecord(ev_fork, 0);
    cudaStreamWaitEvent(s_side, ev_fork, 0);
    zero_cnt_kernel<<<(N + 255) / 256, 256, 0, s_side>>>(N);
    count_kernel<<<eblk, 256, 0, s_side>>>(rows, E);
    scan_kernel<<<1, 1024, 0, s_side>>>(N);
    fill_kernel<<<eblk, 256, 0, s_side>>>(rows, cols, vals, E);
    cudaEventRecord(ev_join, s_side);

    // ---- main: conversions, then pipeline ----
    dim3 wgrid(64, 10);
    cvtw_kernel<<<wgrid, 256>>>(m1_W1, m1_W2, m2_W1, m2_W2, Wu1, Wu2, Wr1, Wr2, Wo1, Wo2, pwh);
    cvtx_kernel<<<(n4 + 255) / 256, 256>>>(x_in, pxinh, n4);

    mlp2_mma_kernel<true><<<nblk, THREADS, smem_mlp>>>(
        pxinh, pwh + 0 * D * D, m1_b1, pwh + 1 * D * D, m1_b2, px, pxh, N);

    cudaStreamWaitEvent(0, ev_join, 0);
    agg_kernel<<<(N * 32 + 255) / 256, 256>>>(pxh, paggh, N);

    mlp2_mma_kernel<false><<<nblk, THREADS, smem_mlp>>>(
        paggh, pwh + 2 * D * D, m2_b1, pwh + 3 * D * D, m2_b2, nullptr, pouth, N);

    dim3 grid01(nblk, 2);
    gate01_mma_kernel<<<grid01, THREADS>>>(pouth, pxh, pwh, bu1, bu2, br1, br2, N);
    gate2_mma_kernel<<<nblk, THREADS>>>(pouth, prxh, pwh, bo1, bo2, (float*)d_out, N);
}